// round 14
// baseline (speedup 1.0000x reference)
#include <cuda_runtime.h>
#include <cuda_bf16.h>
#include <cstdint>

#define BATCH 16
#define T0 64000
#define T1 32000
#define CH1 32
#define T2 16000
#define CH2 64
#define T3 8000
#define CH3 128
#define NH 64
#define NB 64
#define X1R 16140
#define X2R 8072
#define NPB 63        // conv3 tiles per batch = pool partials
#define C3_TILES (BATCH * NPB)
#define C3_BLOCKS 296 // 2 blocks/SM x 148 SMs

typedef unsigned long long ull;

// ---------------- PTX helpers ----------------
__device__ __forceinline__ uint32_t smem_u32(const void* p) {
    uint32_t a;
    asm("{ .reg .u64 t; cvta.to.shared.u64 t, %1; cvt.u32.u64 %0, t; }" : "=r"(a) : "l"(p));
    return a;
}
#define MBAR_INIT(a, n) asm volatile("mbarrier.init.shared.b64 [%0], %1;" :: "r"(a), "r"((uint32_t)(n)) : "memory")
#define MBAR_EXPECT(a, tx) asm volatile("mbarrier.arrive.expect_tx.shared.b64 _, [%0], %1;" :: "r"(a), "r"((uint32_t)(tx)) : "memory")
#define MBAR_ARRIVE(a) asm volatile("mbarrier.arrive.shared.b64 _, [%0];" :: "r"(a) : "memory")
#define MBAR_WAIT(a, ph) do { \
    uint32_t _m = (a), _p = (ph), _d; \
    asm volatile("{ .reg .pred p; mbarrier.try_wait.parity.acquire.cta.shared::cta.b64 p, [%1], %2; selp.b32 %0, 1, 0, p; }" \
        : "=r"(_d) : "r"(_m), "r"(_p) : "memory"); \
    if (!_d) { \
        asm volatile("{ .reg .pred P1; WL_%=: mbarrier.try_wait.parity.acquire.cta.shared::cta.b64 P1, [%0], %1, 0x989680; @P1 bra.uni WD_%=; bra.uni WL_%=; WD_%=: }" \
            :: "r"(_m), "r"(_p) : "memory"); \
    } } while (0)
#define BULK_G2S(dst, src, bytes, mbar) \
    asm volatile("cp.async.bulk.shared::cluster.global.mbarrier::complete_tx::bytes [%0], [%1], %2, [%3];" \
        :: "r"(dst), "l"(src), "r"((uint32_t)(bytes)), "r"(mbar) : "memory")
#define CP16(dst, src) asm volatile("cp.async.cg.shared.global [%0], [%1], 16;" :: "r"(dst), "l"(src))
#define CP_COMMIT() asm volatile("cp.async.commit_group;" ::: "memory")
#define CP_WAIT0() asm volatile("cp.async.wait_group 0;" ::: "memory")

#define LDSM_X4(r, addr) \
    asm volatile("ldmatrix.sync.aligned.m8n8.x4.shared.b16 {%0,%1,%2,%3}, [%4];" \
        : "=r"((r)[0]), "=r"((r)[1]), "=r"((r)[2]), "=r"((r)[3]) : "r"(addr))
#define LDSM_X4_T(r, addr) \
    asm volatile("ldmatrix.sync.aligned.m8n8.x4.trans.shared.b16 {%0,%1,%2,%3}, [%4];" \
        : "=r"((r)[0]), "=r"((r)[1]), "=r"((r)[2]), "=r"((r)[3]) : "r"(addr))
#define MMA16816(d, a, b0, b1) \
    asm volatile("mma.sync.aligned.m16n8k16.row.col.f32.bf16.bf16.f32 " \
        "{%0,%1,%2,%3}, {%4,%5,%6,%7}, {%8,%9}, {%0,%1,%2,%3};" \
        : "+f"((d)[0]), "+f"((d)[1]), "+f"((d)[2]), "+f"((d)[3]) \
        : "r"((a)[0]), "r"((a)[1]), "r"((a)[2]), "r"((a)[3]), "r"(b0), "r"(b1))

// packed f32x2 via fma only
__device__ __forceinline__ ull fma2(ull a, ull b, ull c) {
    ull d;
    asm("fma.rn.f32x2 %0, %1, %2, %3;" : "=l"(d) : "l"(a), "l"(b), "l"(c));
    return d;
}
__device__ __forceinline__ ull pk2(float x, float y) {
    return (ull)(unsigned)__float_as_int(x) | ((ull)(unsigned)__float_as_int(y) << 32);
}

// ---------------- scratch ----------------
__device__ __nv_bfloat16 g_x1e[(size_t)BATCH * X1R * CH1];
__device__ __nv_bfloat16 g_x1o[(size_t)BATCH * X1R * CH1];
__device__ __nv_bfloat16 g_x2e[(size_t)BATCH * X2R * CH2];
__device__ __nv_bfloat16 g_x2o[(size_t)BATCH * X2R * CH2];
__device__ __nv_bfloat16 g_w2s[18 * 32 * 72];
__device__ __nv_bfloat16 g_w3s[18 * 64 * 136];
__device__ float g_poolpart[BATCH * NPB * CH3];
__device__ float g_amps[BATCH * NH];
__device__ float g_nmag[BATCH * NB];
__device__ unsigned g_tick;   // zero-init; reset each launch by last finisher
__device__ unsigned g_fin;

// ---------------- prep ----------------
__global__ void prep_kernel(const float* __restrict__ w2, const float* __restrict__ w3) {
    int tid = blockIdx.x * blockDim.x + threadIdx.x;
    int stride = gridDim.x * blockDim.x;
    for (int i = tid; i < 18 * 32 * 64; i += stride) {
        int co = i & 63, ci = (i >> 6) & 31, tp = i >> 11;
        int k = tp >> 1, p = tp & 1;
        float w = w2[(co * CH1 + ci) * 9 + k];
        __nv_bfloat16 h = __float2bfloat16_rn(w);
        __nv_bfloat16 v = p ? __float2bfloat16_rn(w - __bfloat162float(h)) : h;
        g_w2s[(tp * 32 + ci) * 72 + co] = v;
    }
    for (int i = tid; i < 18 * 64 * 128; i += stride) {
        int co = i & 127, ci = (i >> 7) & 63, tp = i >> 13;
        int k = tp >> 1, p = tp & 1;
        float w = w3[(co * CH2 + ci) * 9 + k];
        __nv_bfloat16 h = __float2bfloat16_rn(w);
        __nv_bfloat16 v = p ? __float2bfloat16_rn(w - __bfloat162float(h)) : h;
        g_w3s[(tp * 64 + ci) * 136 + co] = v;
    }
}

// ---------------- conv1 ----------------
__global__ __launch_bounds__(256) void conv1_kernel(const float* __restrict__ audio,
                                                    const float* __restrict__ w1,
                                                    const float* __restrict__ b1) {
    __shared__ float s_a[264];
    int b = blockIdx.y;
    int t0 = blockIdx.x * 128;
    const float* ab = audio + (size_t)b * T0;
    for (int j = threadIdx.x; j < 263; j += 256) {
        int ti = 2 * t0 - 4 + j;
        s_a[j] = (ti >= 0 && ti < T0) ? ab[ti] : 0.0f;
    }
    __syncthreads();
    int c  = threadIdx.x & 31;
    int tl = threadIdx.x >> 5;
    float w[9];
#pragma unroll
    for (int k = 0; k < 9; k++) w[k] = __ldg(w1 + c * 9 + k);
    float bias = __ldg(b1 + c);
    int tb = tl * 16;
#pragma unroll
    for (int i = 0; i < 16; i++) {
        int tloc = tb + i;
        float acc = bias;
#pragma unroll
        for (int k = 0; k < 9; k++) acc = fmaf(w[k], s_a[2 * tloc + k], acc);
        float v = fmaxf(acc, 0.0f);
        int t = t0 + tloc;
        size_t idx = ((size_t)b * X1R + (t >> 1) + 4) * CH1 + c;
        if (t & 1) g_x1o[idx] = __float2bfloat16_rn(v);
        else       g_x1e[idx] = __float2bfloat16_rn(v);
    }
}

// ---------------- conv2: HMMA, t-tile 256, weights smem-resident ----------------
#define C2_AROWS 260
#define C2_SAE 1024
#define C2_SAO (1024 + C2_AROWS * 80)
#define C2_SW  (1024 + 2 * C2_AROWS * 80)
#define C2_WBYTES (18 * 32 * 144)
#define C2_SMEM (C2_SW + C2_WBYTES)
__global__ __launch_bounds__(256) void conv2_mma(const float* __restrict__ b2v) {
    extern __shared__ char smem[];
    uint32_t sb = smem_u32(smem);
    int tid = threadIdx.x;
    int b = blockIdx.y;
    int t0 = blockIdx.x * 256;
    uint32_t MB = sb;
    if (tid == 0) MBAR_INIT(MB, 1);
    __syncthreads();
    if (tid == 0) {
        MBAR_EXPECT(MB, C2_WBYTES);
        BULK_G2S(sb + C2_SW, (const char*)g_w2s, C2_WBYTES, MB);
    }
    for (int c = tid; c < C2_AROWS * 4; c += 256) {
        int row = c >> 2, part = c & 3;
        size_t so = (((size_t)b * X1R + t0 + 2 + row) * 32 + part * 8) * 2;
        CP16(sb + C2_SAE + row * 80 + part * 16, (const char*)g_x1e + so);
        CP16(sb + C2_SAO + row * 80 + part * 16, (const char*)g_x1o + so);
    }
    CP_COMMIT();
    CP_WAIT0();
    MBAR_WAIT(MB, 0);
    __syncthreads();

    int lane = tid & 31, w = tid >> 5;
    int gid = lane >> 2, tig = lane & 3;
    float d[2][8][4];
#pragma unroll
    for (int i = 0; i < 2; i++)
#pragma unroll
        for (int j = 0; j < 8; j++)
#pragma unroll
            for (int q = 0; q < 4; q++) d[i][j][q] = 0.0f;

    for (int tp = 0; tp < 18; tp++) {
        int k = tp >> 1;
        int par = k & 1;
        int j0 = par ? ((k - 5) / 2 + 2) : ((k - 4) / 2 + 2);
        uint32_t abase = sb + (par ? C2_SAO : C2_SAE);
        uint32_t wtile = sb + C2_SW + tp * 4608;
        uint32_t bb[2][4][4];
#pragma unroll
        for (int ks = 0; ks < 2; ks++)
#pragma unroll
            for (int nb2 = 0; nb2 < 4; nb2++) {
                uint32_t addr = wtile + (ks * 16 + (lane & 15)) * 144 + (nb2 * 16 + (lane >> 4) * 8) * 2;
                LDSM_X4_T(bb[ks][nb2], addr);
            }
#pragma unroll
        for (int ms = 0; ms < 2; ms++) {
            int mrow = w * 32 + ms * 16 + j0;
            uint32_t a[2][4];
#pragma unroll
            for (int ks = 0; ks < 2; ks++) {
                uint32_t addr = abase + (mrow + (lane & 15)) * 80 + (ks * 16 + (lane >> 4) * 8) * 2;
                LDSM_X4(a[ks], addr);
            }
#pragma unroll
            for (int ks = 0; ks < 2; ks++)
#pragma unroll
                for (int nb2 = 0; nb2 < 4; nb2++) {
                    MMA16816(d[ms][nb2 * 2],     a[ks], bb[ks][nb2][0], bb[ks][nb2][1]);
                    MMA16816(d[ms][nb2 * 2 + 1], a[ks], bb[ks][nb2][2], bb[ks][nb2][3]);
                }
        }
    }
#pragma unroll
    for (int ms = 0; ms < 2; ms++)
#pragma unroll
        for (int nb = 0; nb < 8; nb++) {
            int co = nb * 8 + tig * 2;
            float2 bias = *reinterpret_cast<const float2*>(b2v + co);
#pragma unroll
            for (int half = 0; half < 2; half++) {
                int t = t0 + w * 32 + ms * 16 + gid + half * 8;
                if (t < T2) {
                    float v0 = fmaxf(d[ms][nb][half * 2]     + bias.x, 0.0f);
                    float v1 = fmaxf(d[ms][nb][half * 2 + 1] + bias.y, 0.0f);
                    __nv_bfloat162 pv;
                    pv.x = __float2bfloat16_rn(v0);
                    pv.y = __float2bfloat16_rn(v1);
                    size_t idx = ((size_t)b * X2R + (t >> 1) + 4) * CH2 + co;
                    if (t & 1) *reinterpret_cast<__nv_bfloat162*>(&g_x2o[idx]) = pv;
                    else       *reinterpret_cast<__nv_bfloat162*>(&g_x2e[idx]) = pv;
                }
            }
        }
}

// ---------------- conv3: persistent dynamic-ticket HMMA + fused pool ----------------
#define C3_AROWS 132
#define C3_SAE 2048
#define C3_SAO (2048 + C3_AROWS * 144)
#define C3_SW  (2048 + 2 * C3_AROWS * 144)
#define C3_WSTG 17408
#define C3_SMEM (C3_SW + 4 * C3_WSTG)
__global__ __launch_bounds__(256) void conv3_mma(const float* __restrict__ b3v) {
    extern __shared__ char smem[];
    uint32_t sb = smem_u32(smem);
    float* spool = reinterpret_cast<float*>(smem + 1024);
    int tid = threadIdx.x;
    int lane = tid & 31, w = tid >> 5;
    int wm = w >> 2, wn = w & 3;
    int gid = lane >> 2, tig = lane & 3;
    __shared__ unsigned s_tile;

    while (true) {
        if (tid == 0) s_tile = atomicAdd(&g_tick, 1u);
        __syncthreads();
        unsigned tile = s_tile;
        if (tile >= C3_TILES) break;
        int b  = tile / NPB;
        int tx = tile - b * NPB;
        int t0 = tx * 128;

        // fresh barriers for this tile (all prior arrivals/tx drained)
        if (tid == 0) {
            for (int s = 0; s < 4; s++) { MBAR_INIT(sb + 8 * s, 1); MBAR_INIT(sb + 32 + 8 * s, 256); }
        }
        __syncthreads();
        if (tid == 0) {
            for (int s = 0; s < 4; s++) {
                MBAR_EXPECT(sb + 8 * s, C3_WSTG);
                BULK_G2S(sb + C3_SW + s * C3_WSTG, (const char*)g_w3s + s * (size_t)C3_WSTG, C3_WSTG, sb + 8 * s);
            }
        }
        for (int c = tid; c < C3_AROWS * 8; c += 256) {
            int row = c >> 3, part = c & 7;
            size_t so = (((size_t)b * X2R + t0 + 2 + row) * 64 + part * 8) * 2;
            CP16(sb + C3_SAE + row * 144 + part * 16, (const char*)g_x2e + so);
            CP16(sb + C3_SAO + row * 144 + part * 16, (const char*)g_x2o + so);
        }
        CP_COMMIT();
        CP_WAIT0();
        __syncthreads();

        float d[4][4][4];
#pragma unroll
        for (int i = 0; i < 4; i++)
#pragma unroll
            for (int j = 0; j < 4; j++)
#pragma unroll
                for (int q = 0; q < 4; q++) d[i][j][q] = 0.0f;

        for (int tp = 0; tp < 18; tp++) {
            int s = tp & 3;
            MBAR_WAIT(sb + 8 * s, (tp >> 2) & 1);
            int k = tp >> 1;
            int par = k & 1;
            int j0 = par ? ((k - 5) / 2 + 2) : ((k - 4) / 2 + 2);
            uint32_t abase = sb + (par ? C3_SAO : C3_SAE);
            uint32_t wtile = sb + C3_SW + s * C3_WSTG;
            uint32_t bb[2][4][4];
#pragma unroll
            for (int nbl = 0; nbl < 2; nbl++)
#pragma unroll
                for (int ks = 0; ks < 4; ks++) {
                    uint32_t addr = wtile + (ks * 16 + (lane & 15)) * 272
                                  + (wn * 32 + nbl * 16 + (lane >> 4) * 8) * 2;
                    LDSM_X4_T(bb[nbl][ks], addr);
                }
#pragma unroll
            for (int ms = 0; ms < 4; ms++) {
                int mrow = wm * 64 + ms * 16 + j0;
                uint32_t a[4][4];
#pragma unroll
                for (int ks = 0; ks < 4; ks++) {
                    uint32_t addr = abase + (mrow + (lane & 15)) * 144 + (ks * 16 + (lane >> 4) * 8) * 2;
                    LDSM_X4(a[ks], addr);
                }
#pragma unroll
                for (int nbl = 0; nbl < 2; nbl++)
#pragma unroll
                    for (int ks = 0; ks < 4; ks++) {
                        MMA16816(d[ms][nbl * 2],     a[ks], bb[nbl][ks][0], bb[nbl][ks][1]);
                        MMA16816(d[ms][nbl * 2 + 1], a[ks], bb[nbl][ks][2], bb[nbl][ks][3]);
                    }
            }
            MBAR_ARRIVE(sb + 32 + 8 * s);
            if (tid == 0 && tp + 4 < 18) {
                MBAR_WAIT(sb + 32 + 8 * s, (tp >> 2) & 1);
                MBAR_EXPECT(sb + 8 * s, C3_WSTG);
                BULK_G2S(sb + C3_SW + s * C3_WSTG, (const char*)g_w3s + (tp + 4) * (size_t)C3_WSTG, C3_WSTG, sb + 8 * s);
            }
        }

        float psx[4], psy[4];
#pragma unroll
        for (int nb = 0; nb < 4; nb++) {
            int co = wn * 32 + nb * 8 + tig * 2;
            float2 bias = *reinterpret_cast<const float2*>(b3v + co);
            float sx = 0.0f, sy = 0.0f;
#pragma unroll
            for (int ms = 0; ms < 4; ms++)
#pragma unroll
                for (int hz = 0; hz < 2; hz++) {
                    int t = t0 + wm * 64 + ms * 16 + gid + hz * 8;
                    if (t < T3) {
                        sx += fmaxf(d[ms][nb][hz * 2]     + bias.x, 0.0f);
                        sy += fmaxf(d[ms][nb][hz * 2 + 1] + bias.y, 0.0f);
                    }
                }
            psx[nb] = sx; psy[nb] = sy;
        }
#pragma unroll
        for (int off = 4; off < 32; off <<= 1)
#pragma unroll
            for (int nb = 0; nb < 4; nb++) {
                psx[nb] += __shfl_xor_sync(0xffffffffu, psx[nb], off);
                psy[nb] += __shfl_xor_sync(0xffffffffu, psy[nb], off);
            }
        if (lane < 4) {
#pragma unroll
            for (int nb = 0; nb < 4; nb++) {
                int co = wn * 32 + nb * 8 + lane * 2;
                spool[wm * 128 + co]     = psx[nb];
                spool[wm * 128 + co + 1] = psy[nb];
            }
        }
        __syncthreads();
        if (tid < 128)
            g_poolpart[(b * NPB + tx) * CH3 + tid] = spool[tid] + spool[128 + tid];
        // loop-top __syncthreads orders this store before smem reuse
    }
    // reset counters for graph replay; the 296th finisher runs strictly after
    // every block's final ticket read (ordered by per-thread program order)
    if (tid == 0) {
        unsigned f = atomicAdd(&g_fin, 1u);
        if (f == C3_BLOCKS - 1) { g_tick = 0; g_fin = 0; }
    }
}

// ---------------- head (round-7 form) ----------------
__global__ void head_kernel(const float* __restrict__ wl, const float* __restrict__ bl) {
    __shared__ float sp[128];
    __shared__ float s_amp[64];
    __shared__ float s_sum;
    int b = blockIdx.x, j = threadIdx.x;
    float s = 0.0f;
    for (int p = 0; p < NPB; p++) s += g_poolpart[(b * NPB + p) * CH3 + j];
    sp[j] = s * (1.0f / 8000.0f);
    __syncthreads();
    float dot = __ldg(bl + j);
    for (int c = 0; c < 128; c++) dot = fmaf(sp[c], __ldg(wl + j * 128 + c), dot);
    if (j < 64) s_amp[j] = fmaxf(dot, 0.0f);
    __syncthreads();
    if (j == 0) {
        float t = 0.0f;
        for (int h = 0; h < 64; h++) t += s_amp[h];
        s_sum = t + 1e-6f;
    }
    __syncthreads();
    if (j < 64) g_amps[b * 64 + j] = s_amp[j] / s_sum;
    else        g_nmag[b * 64 + (j - 64)] = dot;
}

// ---------------- synth: packed f32x2 harmonic pairs ----------------
__global__ __launch_bounds__(256) void synth_kernel(const float* __restrict__ f0,
                                                    const float* __restrict__ wn,
                                                    float* __restrict__ out) {
    __shared__ __align__(16) float s_amps[64];
    __shared__ float s_nm[64];
    int b = blockIdx.y;
    if (threadIdx.x < 64)       s_amps[threadIdx.x]    = g_amps[b * 64 + threadIdx.x];
    else if (threadIdx.x < 128) s_nm[threadIdx.x - 64] = g_nmag[b * 64 + threadIdx.x - 64];
    __syncthreads();
    int t = blockIdx.x * 256 + threadIdx.x;

    constexpr float DELTA  = 4.0f / 63999.0f;
    constexpr float TWO_PI = 6.283185307179586f;
    float tf  = (float)t * DELTA;
    float a   = TWO_PI * f0[(size_t)b * T0 + t];

    constexpr double PIO2_D = 1.5707963267948966192313216916397514;
    constexpr float RC1 = (float)PIO2_D;
    constexpr float RC2 = (float)(PIO2_D - (double)RC1);
    constexpr float INV_PIO2 = 0.63661977236758134308f;
    constexpr float MAGIC = 12582912.0f;

    const ull ONE2   = pk2(1.0f, 1.0f);
    const ull ZERO2  = 0ULL;
    const ull INV2   = pk2(INV_PIO2, INV_PIO2);
    const ull MAG2   = pk2(MAGIC, MAGIC);
    const ull NMAG2  = pk2(-MAGIC, -MAGIC);
    const ull NRC1_2 = pk2(-RC1, -RC1);
    const ull NRC2_2 = pk2(-RC2, -RC2);
    const ull SC1_2  = pk2(-1.9515295891e-4f, -1.9515295891e-4f);
    const ull SC2_2  = pk2(8.3321608736e-3f,  8.3321608736e-3f);
    const ull SC3_2  = pk2(-1.6666654611e-1f, -1.6666654611e-1f);
    const ull CC1_2  = pk2(2.443315711809948e-5f,  2.443315711809948e-5f);
    const ull CC2_2  = pk2(-1.388731625493765e-3f, -1.388731625493765e-3f);
    const ull CC3_2  = pk2(4.166664568298827e-2f,  4.166664568298827e-2f);
    const ull NHALF2 = pk2(-0.5f, -0.5f);
    const ull TWO2   = pk2(2.0f, 2.0f);

    ull a2  = pk2(a, a);
    ull tf2 = pk2(tf, tf);
    ull h2  = pk2(1.0f, 2.0f);
    ull acc2 = ZERO2;
    const ull* amps2 = reinterpret_cast<const ull*>(s_amps);

#pragma unroll
    for (int p = 0; p < 32; p++) {
        ull bh2 = fma2(a2, h2, ZERO2);
        ull x2  = fma2(bh2, tf2, ZERO2);
        ull kr2 = fma2(x2, INV2, MAG2);
        unsigned q0 = (unsigned)kr2, q1 = (unsigned)(kr2 >> 32);
        ull kf2 = fma2(kr2, ONE2, NMAG2);
        ull r2  = fma2(kf2, NRC1_2, x2);
        r2      = fma2(kf2, NRC2_2, r2);
        ull z2  = fma2(r2, r2, ZERO2);
        ull ps2 = fma2(SC1_2, z2, SC2_2);
        ps2     = fma2(ps2, z2, SC3_2);
        ps2     = fma2(ps2, z2, ZERO2);
        ull sr2 = fma2(ps2, r2, r2);
        ull pc2 = fma2(CC1_2, z2, CC2_2);
        pc2     = fma2(pc2, z2, CC3_2);
        pc2     = fma2(pc2, z2, NHALF2);
        ull cr2 = fma2(pc2, z2, ONE2);
        unsigned s0 = (unsigned)sr2, s1 = (unsigned)(sr2 >> 32);
        unsigned c0 = (unsigned)cr2, c1 = (unsigned)(cr2 >> 32);
        unsigned v0 = (q0 & 1u) ? c0 : s0;  v0 ^= (q0 << 30) & 0x80000000u;
        unsigned v1 = (q1 & 1u) ? c1 : s1;  v1 ^= (q1 << 30) & 0x80000000u;
        ull v2 = (ull)v0 | ((ull)v1 << 32);
        acc2 = fma2(amps2[p], v2, acc2);
        h2 = fma2(h2, ONE2, TWO2);
    }
    float acc = __int_as_float((int)(unsigned)acc2)
              + __int_as_float((int)(unsigned)(acc2 >> 32));

    int bin = t / 1000;
    float shaped = wn[(size_t)b * T0 + t] * s_nm[bin];
    out[(size_t)b * T0 + t] = acc + shaped;
}

extern "C" void kernel_launch(void* const* d_in, const int* in_sizes, int n_in,
                              void* d_out, int out_size) {
    (void)in_sizes; (void)n_in; (void)out_size;
    const float* audio = (const float*)d_in[0];
    const float* f0    = (const float*)d_in[1];
    const float* wn    = (const float*)d_in[2];
    const float* w1    = (const float*)d_in[3];
    const float* b1    = (const float*)d_in[4];
    const float* w2    = (const float*)d_in[5];
    const float* b2    = (const float*)d_in[6];
    const float* w3    = (const float*)d_in[7];
    const float* b3    = (const float*)d_in[8];
    const float* wl    = (const float*)d_in[9];
    const float* bl    = (const float*)d_in[10];
    float* out = (float*)d_out;

    cudaFuncSetAttribute(conv2_mma, cudaFuncAttributeMaxDynamicSharedMemorySize, C2_SMEM);
    cudaFuncSetAttribute(conv3_mma, cudaFuncAttributeMaxDynamicSharedMemorySize, C3_SMEM);

    prep_kernel<<<64, 256>>>(w2, w3);
    conv1_kernel<<<dim3(250, 16), 256>>>(audio, w1, b1);
    conv2_mma<<<dim3(63, 16), 256, C2_SMEM>>>(b2);
    conv3_mma<<<C3_BLOCKS, 256, C3_SMEM>>>(b3);
    head_kernel<<<16, 128>>>(wl, bl);
    synth_kernel<<<dim3(250, 16), 256>>>(f0, wn, out);
}

// round 15
// speedup vs baseline: 1.0551x; 1.0551x over previous
#include <cuda_runtime.h>
#include <cuda_bf16.h>
#include <cstdint>

#define BATCH 16
#define T0 64000
#define T1 32000
#define CH1 32
#define T2 16000
#define CH2 64
#define T3 8000
#define CH3 128
#define NH 64
#define NB 64
#define X1R 16140
#define X2R 8072
#define NPB 63      // conv3 blocks per batch = pool partials

typedef unsigned long long ull;

// ---------------- PTX helpers ----------------
__device__ __forceinline__ uint32_t smem_u32(const void* p) {
    uint32_t a;
    asm("{ .reg .u64 t; cvta.to.shared.u64 t, %1; cvt.u32.u64 %0, t; }" : "=r"(a) : "l"(p));
    return a;
}
#define MBAR_INIT(a, n) asm volatile("mbarrier.init.shared.b64 [%0], %1;" :: "r"(a), "r"((uint32_t)(n)) : "memory")
#define MBAR_EXPECT(a, tx) asm volatile("mbarrier.arrive.expect_tx.shared.b64 _, [%0], %1;" :: "r"(a), "r"((uint32_t)(tx)) : "memory")
#define MBAR_ARRIVE(a) asm volatile("mbarrier.arrive.shared.b64 _, [%0];" :: "r"(a) : "memory")
#define MBAR_WAIT(a, ph) do { \
    uint32_t _m = (a), _p = (ph), _d; \
    asm volatile("{ .reg .pred p; mbarrier.try_wait.parity.acquire.cta.shared::cta.b64 p, [%1], %2; selp.b32 %0, 1, 0, p; }" \
        : "=r"(_d) : "r"(_m), "r"(_p) : "memory"); \
    if (!_d) { \
        asm volatile("{ .reg .pred P1; WL_%=: mbarrier.try_wait.parity.acquire.cta.shared::cta.b64 P1, [%0], %1, 0x989680; @P1 bra.uni WD_%=; bra.uni WL_%=; WD_%=: }" \
            :: "r"(_m), "r"(_p) : "memory"); \
    } } while (0)
#define BULK_G2S(dst, src, bytes, mbar) \
    asm volatile("cp.async.bulk.shared::cluster.global.mbarrier::complete_tx::bytes [%0], [%1], %2, [%3];" \
        :: "r"(dst), "l"(src), "r"((uint32_t)(bytes)), "r"(mbar) : "memory")
#define CP16(dst, src) asm volatile("cp.async.cg.shared.global [%0], [%1], 16;" :: "r"(dst), "l"(src))
#define CP_COMMIT() asm volatile("cp.async.commit_group;" ::: "memory")
#define CP_WAIT0() asm volatile("cp.async.wait_group 0;" ::: "memory")

#define LDSM_X4(r, addr) \
    asm volatile("ldmatrix.sync.aligned.m8n8.x4.shared.b16 {%0,%1,%2,%3}, [%4];" \
        : "=r"((r)[0]), "=r"((r)[1]), "=r"((r)[2]), "=r"((r)[3]) : "r"(addr))
#define LDSM_X4_T(r, addr) \
    asm volatile("ldmatrix.sync.aligned.m8n8.x4.trans.shared.b16 {%0,%1,%2,%3}, [%4];" \
        : "=r"((r)[0]), "=r"((r)[1]), "=r"((r)[2]), "=r"((r)[3]) : "r"(addr))
#define MMA16816(d, a, b0, b1) \
    asm volatile("mma.sync.aligned.m16n8k16.row.col.f32.bf16.bf16.f32 " \
        "{%0,%1,%2,%3}, {%4,%5,%6,%7}, {%8,%9}, {%0,%1,%2,%3};" \
        : "+f"((d)[0]), "+f"((d)[1]), "+f"((d)[2]), "+f"((d)[3]) \
        : "r"((a)[0]), "r"((a)[1]), "r"((a)[2]), "r"((a)[3]), "r"(b0), "r"(b1))

// packed f32x2 via fma only
__device__ __forceinline__ ull fma2(ull a, ull b, ull c) {
    ull d;
    asm("fma.rn.f32x2 %0, %1, %2, %3;" : "=l"(d) : "l"(a), "l"(b), "l"(c));
    return d;
}
__device__ __forceinline__ ull pk2(float x, float y) {
    return (ull)(unsigned)__float_as_int(x) | ((ull)(unsigned)__float_as_int(y) << 32);
}

// ---------------- scratch ----------------
__device__ __nv_bfloat16 g_x1e[(size_t)BATCH * X1R * CH1];
__device__ __nv_bfloat16 g_x1o[(size_t)BATCH * X1R * CH1];
__device__ __nv_bfloat16 g_x2e[(size_t)BATCH * X2R * CH2];
__device__ __nv_bfloat16 g_x2o[(size_t)BATCH * X2R * CH2];
__device__ __nv_bfloat16 g_w2s[18 * 32 * 72];
__device__ __nv_bfloat16 g_w3s[18 * 64 * 136];
__device__ float g_poolpart[BATCH * NPB * CH3];
__device__ float g_amps[BATCH * NH];
__device__ float g_nmag[BATCH * NB];

// ---------------- prep ----------------
__global__ void prep_kernel(const float* __restrict__ w2, const float* __restrict__ w3) {
    int tid = blockIdx.x * blockDim.x + threadIdx.x;
    int stride = gridDim.x * blockDim.x;
    for (int i = tid; i < 18 * 32 * 64; i += stride) {
        int co = i & 63, ci = (i >> 6) & 31, tp = i >> 11;
        int k = tp >> 1, p = tp & 1;
        float w = w2[(co * CH1 + ci) * 9 + k];
        __nv_bfloat16 h = __float2bfloat16_rn(w);
        __nv_bfloat16 v = p ? __float2bfloat16_rn(w - __bfloat162float(h)) : h;
        g_w2s[(tp * 32 + ci) * 72 + co] = v;
    }
    for (int i = tid; i < 18 * 64 * 128; i += stride) {
        int co = i & 127, ci = (i >> 7) & 63, tp = i >> 13;
        int k = tp >> 1, p = tp & 1;
        float w = w3[(co * CH2 + ci) * 9 + k];
        __nv_bfloat16 h = __float2bfloat16_rn(w);
        __nv_bfloat16 v = p ? __float2bfloat16_rn(w - __bfloat162float(h)) : h;
        g_w3s[(tp * 64 + ci) * 136 + co] = v;
    }
}

// ---------------- conv1 ----------------
__global__ __launch_bounds__(256) void conv1_kernel(const float* __restrict__ audio,
                                                    const float* __restrict__ w1,
                                                    const float* __restrict__ b1) {
    __shared__ float s_a[264];
    int b = blockIdx.y;
    int t0 = blockIdx.x * 128;
    const float* ab = audio + (size_t)b * T0;
    for (int j = threadIdx.x; j < 263; j += 256) {
        int ti = 2 * t0 - 4 + j;
        s_a[j] = (ti >= 0 && ti < T0) ? ab[ti] : 0.0f;
    }
    __syncthreads();
    int c  = threadIdx.x & 31;
    int tl = threadIdx.x >> 5;
    float w[9];
#pragma unroll
    for (int k = 0; k < 9; k++) w[k] = __ldg(w1 + c * 9 + k);
    float bias = __ldg(b1 + c);
    int tb = tl * 16;
#pragma unroll
    for (int i = 0; i < 16; i++) {
        int tloc = tb + i;
        float acc = bias;
#pragma unroll
        for (int k = 0; k < 9; k++) acc = fmaf(w[k], s_a[2 * tloc + k], acc);
        float v = fmaxf(acc, 0.0f);
        int t = t0 + tloc;
        size_t idx = ((size_t)b * X1R + (t >> 1) + 4) * CH1 + c;
        if (t & 1) g_x1o[idx] = __float2bfloat16_rn(v);
        else       g_x1e[idx] = __float2bfloat16_rn(v);
    }
}

// ---------------- conv2: HMMA, t-tile 256, weights STREAMED (4-stage ring) ----------------
// smem: [0,64) mbars | A even 260x80 @1024 | A odd | ring 4 x 4608
#define C2_AROWS 260
#define C2_SAE 1024
#define C2_SAO (1024 + C2_AROWS * 80)
#define C2_SW  (1024 + 2 * C2_AROWS * 80)
#define C2_WSTG 4608
#define C2_SMEM (C2_SW + 4 * C2_WSTG)
__global__ __launch_bounds__(256) void conv2_mma(const float* __restrict__ b2v) {
    extern __shared__ char smem[];
    uint32_t sb = smem_u32(smem);
    int tid = threadIdx.x;
    int b = blockIdx.y;
    int t0 = blockIdx.x * 256;
    // barriers: rdy[s] at sb + 8*s, empty[s] at sb + 32 + 8*s
    if (tid == 0) {
        for (int s = 0; s < 4; s++) { MBAR_INIT(sb + 8 * s, 1); MBAR_INIT(sb + 32 + 8 * s, 256); }
    }
    __syncthreads();
    if (tid == 0) {
        for (int s = 0; s < 4; s++) {
            MBAR_EXPECT(sb + 8 * s, C2_WSTG);
            BULK_G2S(sb + C2_SW + s * C2_WSTG, (const char*)g_w2s + s * (size_t)C2_WSTG, C2_WSTG, sb + 8 * s);
        }
    }
    for (int c = tid; c < C2_AROWS * 4; c += 256) {
        int row = c >> 2, part = c & 3;
        size_t so = (((size_t)b * X1R + t0 + 2 + row) * 32 + part * 8) * 2;
        CP16(sb + C2_SAE + row * 80 + part * 16, (const char*)g_x1e + so);
        CP16(sb + C2_SAO + row * 80 + part * 16, (const char*)g_x1o + so);
    }
    CP_COMMIT();
    CP_WAIT0();
    __syncthreads();

    int lane = tid & 31, w = tid >> 5;
    int gid = lane >> 2, tig = lane & 3;
    float d[2][8][4];
#pragma unroll
    for (int i = 0; i < 2; i++)
#pragma unroll
        for (int j = 0; j < 8; j++)
#pragma unroll
            for (int q = 0; q < 4; q++) d[i][j][q] = 0.0f;

    for (int tp = 0; tp < 18; tp++) {
        int s = tp & 3;
        MBAR_WAIT(sb + 8 * s, (tp >> 2) & 1);
        int k = tp >> 1;
        int par = k & 1;
        int j0 = par ? ((k - 5) / 2 + 2) : ((k - 4) / 2 + 2);
        uint32_t abase = sb + (par ? C2_SAO : C2_SAE);
        uint32_t wtile = sb + C2_SW + s * C2_WSTG;
        uint32_t bb[2][4][4];
#pragma unroll
        for (int ks = 0; ks < 2; ks++)
#pragma unroll
            for (int nb2 = 0; nb2 < 4; nb2++) {
                uint32_t addr = wtile + (ks * 16 + (lane & 15)) * 144 + (nb2 * 16 + (lane >> 4) * 8) * 2;
                LDSM_X4_T(bb[ks][nb2], addr);
            }
#pragma unroll
        for (int ms = 0; ms < 2; ms++) {
            int mrow = w * 32 + ms * 16 + j0;
            uint32_t a[2][4];
#pragma unroll
            for (int ks = 0; ks < 2; ks++) {
                uint32_t addr = abase + (mrow + (lane & 15)) * 80 + (ks * 16 + (lane >> 4) * 8) * 2;
                LDSM_X4(a[ks], addr);
            }
#pragma unroll
            for (int ks = 0; ks < 2; ks++)
#pragma unroll
                for (int nb2 = 0; nb2 < 4; nb2++) {
                    MMA16816(d[ms][nb2 * 2],     a[ks], bb[ks][nb2][0], bb[ks][nb2][1]);
                    MMA16816(d[ms][nb2 * 2 + 1], a[ks], bb[ks][nb2][2], bb[ks][nb2][3]);
                }
        }
        MBAR_ARRIVE(sb + 32 + 8 * s);
        if (tid == 0 && tp + 4 < 18) {
            MBAR_WAIT(sb + 32 + 8 * s, (tp >> 2) & 1);
            MBAR_EXPECT(sb + 8 * s, C2_WSTG);
            BULK_G2S(sb + C2_SW + s * C2_WSTG, (const char*)g_w2s + (tp + 4) * (size_t)C2_WSTG, C2_WSTG, sb + 8 * s);
        }
    }
#pragma unroll
    for (int ms = 0; ms < 2; ms++)
#pragma unroll
        for (int nb = 0; nb < 8; nb++) {
            int co = nb * 8 + tig * 2;
            float2 bias = *reinterpret_cast<const float2*>(b2v + co);
#pragma unroll
            for (int half = 0; half < 2; half++) {
                int t = t0 + w * 32 + ms * 16 + gid + half * 8;
                if (t < T2) {
                    float v0 = fmaxf(d[ms][nb][half * 2]     + bias.x, 0.0f);
                    float v1 = fmaxf(d[ms][nb][half * 2 + 1] + bias.y, 0.0f);
                    __nv_bfloat162 pv;
                    pv.x = __float2bfloat16_rn(v0);
                    pv.y = __float2bfloat16_rn(v1);
                    size_t idx = ((size_t)b * X2R + (t >> 1) + 4) * CH2 + co;
                    if (t & 1) *reinterpret_cast<__nv_bfloat162*>(&g_x2o[idx]) = pv;
                    else       *reinterpret_cast<__nv_bfloat162*>(&g_x2e[idx]) = pv;
                }
            }
        }
}

// ---------------- conv3: HMMA 2Mx4N warps, fused mean-pool epilogue (round-13) ----------------
#define C3_AROWS 132
#define C3_SAE 2048
#define C3_SAO (2048 + C3_AROWS * 144)
#define C3_SW  (2048 + 2 * C3_AROWS * 144)
#define C3_WSTG 17408
#define C3_SMEM (C3_SW + 4 * C3_WSTG)
__global__ __launch_bounds__(256) void conv3_mma(const float* __restrict__ b3v) {
    extern __shared__ char smem[];
    uint32_t sb = smem_u32(smem);
    float* spool = reinterpret_cast<float*>(smem + 1024);
    int tid = threadIdx.x;
    int b = blockIdx.y;
    int t0 = blockIdx.x * 128;
    if (tid == 0) {
        for (int s = 0; s < 4; s++) { MBAR_INIT(sb + 8 * s, 1); MBAR_INIT(sb + 32 + 8 * s, 256); }
    }
    __syncthreads();
    if (tid == 0) {
        for (int s = 0; s < 4; s++) {
            MBAR_EXPECT(sb + 8 * s, C3_WSTG);
            BULK_G2S(sb + C3_SW + s * C3_WSTG, (const char*)g_w3s + s * (size_t)C3_WSTG, C3_WSTG, sb + 8 * s);
        }
    }
    for (int c = tid; c < C3_AROWS * 8; c += 256) {
        int row = c >> 3, part = c & 7;
        size_t so = (((size_t)b * X2R + t0 + 2 + row) * 64 + part * 8) * 2;
        CP16(sb + C3_SAE + row * 144 + part * 16, (const char*)g_x2e + so);
        CP16(sb + C3_SAO + row * 144 + part * 16, (const char*)g_x2o + so);
    }
    CP_COMMIT();
    CP_WAIT0();
    __syncthreads();

    int lane = tid & 31, w = tid >> 5;
    int wm = w >> 2, wn = w & 3;
    int gid = lane >> 2, tig = lane & 3;
    float d[4][4][4];
#pragma unroll
    for (int i = 0; i < 4; i++)
#pragma unroll
        for (int j = 0; j < 4; j++)
#pragma unroll
            for (int q = 0; q < 4; q++) d[i][j][q] = 0.0f;

    for (int tp = 0; tp < 18; tp++) {
        int s = tp & 3;
        MBAR_WAIT(sb + 8 * s, (tp >> 2) & 1);
        int k = tp >> 1;
        int par = k & 1;
        int j0 = par ? ((k - 5) / 2 + 2) : ((k - 4) / 2 + 2);
        uint32_t abase = sb + (par ? C3_SAO : C3_SAE);
        uint32_t wtile = sb + C3_SW + s * C3_WSTG;
        uint32_t bb[2][4][4];
#pragma unroll
        for (int nbl = 0; nbl < 2; nbl++)
#pragma unroll
            for (int ks = 0; ks < 4; ks++) {
                uint32_t addr = wtile + (ks * 16 + (lane & 15)) * 272
                              + (wn * 32 + nbl * 16 + (lane >> 4) * 8) * 2;
                LDSM_X4_T(bb[nbl][ks], addr);
            }
#pragma unroll
        for (int ms = 0; ms < 4; ms++) {
            int mrow = wm * 64 + ms * 16 + j0;
            uint32_t a[4][4];
#pragma unroll
            for (int ks = 0; ks < 4; ks++) {
                uint32_t addr = abase + (mrow + (lane & 15)) * 144 + (ks * 16 + (lane >> 4) * 8) * 2;
                LDSM_X4(a[ks], addr);
            }
#pragma unroll
            for (int nbl = 0; nbl < 2; nbl++)
#pragma unroll
                for (int ks = 0; ks < 4; ks++) {
                    MMA16816(d[ms][nbl * 2],     a[ks], bb[nbl][ks][0], bb[nbl][ks][1]);
                    MMA16816(d[ms][nbl * 2 + 1], a[ks], bb[nbl][ks][2], bb[nbl][ks][3]);
                }
        }
        MBAR_ARRIVE(sb + 32 + 8 * s);
        if (tid == 0 && tp + 4 < 18) {
            MBAR_WAIT(sb + 32 + 8 * s, (tp >> 2) & 1);
            MBAR_EXPECT(sb + 8 * s, C3_WSTG);
            BULK_G2S(sb + C3_SW + s * C3_WSTG, (const char*)g_w3s + (tp + 4) * (size_t)C3_WSTG, C3_WSTG, sb + 8 * s);
        }
    }

    float psx[4], psy[4];
#pragma unroll
    for (int nb = 0; nb < 4; nb++) {
        int co = wn * 32 + nb * 8 + tig * 2;
        float2 bias = *reinterpret_cast<const float2*>(b3v + co);
        float sx = 0.0f, sy = 0.0f;
#pragma unroll
        for (int ms = 0; ms < 4; ms++)
#pragma unroll
            for (int hz = 0; hz < 2; hz++) {
                int t = t0 + wm * 64 + ms * 16 + gid + hz * 8;
                if (t < T3) {
                    sx += fmaxf(d[ms][nb][hz * 2]     + bias.x, 0.0f);
                    sy += fmaxf(d[ms][nb][hz * 2 + 1] + bias.y, 0.0f);
                }
            }
        psx[nb] = sx; psy[nb] = sy;
    }
#pragma unroll
    for (int off = 4; off < 32; off <<= 1)
#pragma unroll
        for (int nb = 0; nb < 4; nb++) {
            psx[nb] += __shfl_xor_sync(0xffffffffu, psx[nb], off);
            psy[nb] += __shfl_xor_sync(0xffffffffu, psy[nb], off);
        }
    if (lane < 4) {
#pragma unroll
        for (int nb = 0; nb < 4; nb++) {
            int co = wn * 32 + nb * 8 + lane * 2;
            spool[wm * 128 + co]     = psx[nb];
            spool[wm * 128 + co + 1] = psy[nb];
        }
    }
    __syncthreads();
    if (tid < 128)
        g_poolpart[(b * NPB + blockIdx.x) * CH3 + tid] = spool[tid] + spool[128 + tid];
}

// ---------------- head ----------------
__global__ void head_kernel(const float* __restrict__ wl, const float* __restrict__ bl) {
    __shared__ float sp[128];
    __shared__ float s_amp[64];
    __shared__ float s_sum;
    int b = blockIdx.x, j = threadIdx.x;
    float s = 0.0f;
    for (int p = 0; p < NPB; p++) s += g_poolpart[(b * NPB + p) * CH3 + j];
    sp[j] = s * (1.0f / 8000.0f);
    __syncthreads();
    float dot = __ldg(bl + j);
    for (int c = 0; c < 128; c++) dot = fmaf(sp[c], __ldg(wl + j * 128 + c), dot);
    if (j < 64) s_amp[j] = fmaxf(dot, 0.0f);
    __syncthreads();
    if (j == 0) {
        float t = 0.0f;
        for (int h = 0; h < 64; h++) t += s_amp[h];
        s_sum = t + 1e-6f;
    }
    __syncthreads();
    if (j < 64) g_amps[b * 64 + j] = s_amp[j] / s_sum;
    else        g_nmag[b * 64 + (j - 64)] = dot;
}

// ---------------- synth: packed f32x2 harmonic pairs ----------------
__global__ __launch_bounds__(256) void synth_kernel(const float* __restrict__ f0,
                                                    const float* __restrict__ wn,
                                                    float* __restrict__ out) {
    __shared__ __align__(16) float s_amps[64];
    __shared__ float s_nm[64];
    int b = blockIdx.y;
    if (threadIdx.x < 64)       s_amps[threadIdx.x]    = g_amps[b * 64 + threadIdx.x];
    else if (threadIdx.x < 128) s_nm[threadIdx.x - 64] = g_nmag[b * 64 + threadIdx.x - 64];
    __syncthreads();
    int t = blockIdx.x * 256 + threadIdx.x;

    constexpr float DELTA  = 4.0f / 63999.0f;
    constexpr float TWO_PI = 6.283185307179586f;
    float tf  = (float)t * DELTA;
    float a   = TWO_PI * f0[(size_t)b * T0 + t];

    constexpr double PIO2_D = 1.5707963267948966192313216916397514;
    constexpr float RC1 = (float)PIO2_D;
    constexpr float RC2 = (float)(PIO2_D - (double)RC1);
    constexpr float INV_PIO2 = 0.63661977236758134308f;
    constexpr float MAGIC = 12582912.0f;

    const ull ONE2   = pk2(1.0f, 1.0f);
    const ull ZERO2  = 0ULL;
    const ull INV2   = pk2(INV_PIO2, INV_PIO2);
    const ull MAG2   = pk2(MAGIC, MAGIC);
    const ull NMAG2  = pk2(-MAGIC, -MAGIC);
    const ull NRC1_2 = pk2(-RC1, -RC1);
    const ull NRC2_2 = pk2(-RC2, -RC2);
    const ull SC1_2  = pk2(-1.9515295891e-4f, -1.9515295891e-4f);
    const ull SC2_2  = pk2(8.3321608736e-3f,  8.3321608736e-3f);
    const ull SC3_2  = pk2(-1.6666654611e-1f, -1.6666654611e-1f);
    const ull CC1_2  = pk2(2.443315711809948e-5f,  2.443315711809948e-5f);
    const ull CC2_2  = pk2(-1.388731625493765e-3f, -1.388731625493765e-3f);
    const ull CC3_2  = pk2(4.166664568298827e-2f,  4.166664568298827e-2f);
    const ull NHALF2 = pk2(-0.5f, -0.5f);
    const ull TWO2   = pk2(2.0f, 2.0f);

    ull a2  = pk2(a, a);
    ull tf2 = pk2(tf, tf);
    ull h2  = pk2(1.0f, 2.0f);
    ull acc2 = ZERO2;
    const ull* amps2 = reinterpret_cast<const ull*>(s_amps);

#pragma unroll
    for (int p = 0; p < 32; p++) {
        ull bh2 = fma2(a2, h2, ZERO2);
        ull x2  = fma2(bh2, tf2, ZERO2);
        ull kr2 = fma2(x2, INV2, MAG2);
        unsigned q0 = (unsigned)kr2, q1 = (unsigned)(kr2 >> 32);
        ull kf2 = fma2(kr2, ONE2, NMAG2);
        ull r2  = fma2(kf2, NRC1_2, x2);
        r2      = fma2(kf2, NRC2_2, r2);
        ull z2  = fma2(r2, r2, ZERO2);
        ull ps2 = fma2(SC1_2, z2, SC2_2);
        ps2     = fma2(ps2, z2, SC3_2);
        ps2     = fma2(ps2, z2, ZERO2);
        ull sr2 = fma2(ps2, r2, r2);
        ull pc2 = fma2(CC1_2, z2, CC2_2);
        pc2     = fma2(pc2, z2, CC3_2);
        pc2     = fma2(pc2, z2, NHALF2);
        ull cr2 = fma2(pc2, z2, ONE2);
        unsigned s0 = (unsigned)sr2, s1 = (unsigned)(sr2 >> 32);
        unsigned c0 = (unsigned)cr2, c1 = (unsigned)(cr2 >> 32);
        unsigned v0 = (q0 & 1u) ? c0 : s0;  v0 ^= (q0 << 30) & 0x80000000u;
        unsigned v1 = (q1 & 1u) ? c1 : s1;  v1 ^= (q1 << 30) & 0x80000000u;
        ull v2 = (ull)v0 | ((ull)v1 << 32);
        acc2 = fma2(amps2[p], v2, acc2);
        h2 = fma2(h2, ONE2, TWO2);
    }
    float acc = __int_as_float((int)(unsigned)acc2)
              + __int_as_float((int)(unsigned)(acc2 >> 32));

    int bin = t / 1000;
    float shaped = wn[(size_t)b * T0 + t] * s_nm[bin];
    out[(size_t)b * T0 + t] = acc + shaped;
}

extern "C" void kernel_launch(void* const* d_in, const int* in_sizes, int n_in,
                              void* d_out, int out_size) {
    (void)in_sizes; (void)n_in; (void)out_size;
    const float* audio = (const float*)d_in[0];
    const float* f0    = (const float*)d_in[1];
    const float* wn    = (const float*)d_in[2];
    const float* w1    = (const float*)d_in[3];
    const float* b1    = (const float*)d_in[4];
    const float* w2    = (const float*)d_in[5];
    const float* b2    = (const float*)d_in[6];
    const float* w3    = (const float*)d_in[7];
    const float* b3    = (const float*)d_in[8];
    const float* wl    = (const float*)d_in[9];
    const float* bl    = (const float*)d_in[10];
    float* out = (float*)d_out;

    cudaFuncSetAttribute(conv2_mma, cudaFuncAttributeMaxDynamicSharedMemorySize, C2_SMEM);
    cudaFuncSetAttribute(conv3_mma, cudaFuncAttributeMaxDynamicSharedMemorySize, C3_SMEM);

    prep_kernel<<<64, 256>>>(w2, w3);
    conv1_kernel<<<dim3(250, 16), 256>>>(audio, w1, b1);
    conv2_mma<<<dim3(63, 16), 256, C2_SMEM>>>(b2);
    conv3_mma<<<dim3(63, 16), 256, C3_SMEM>>>(b3);
    head_kernel<<<16, 128>>>(wl, bl);
    synth_kernel<<<dim3(250, 16), 256>>>(f0, wn, out);
}

// round 16
// speedup vs baseline: 1.0568x; 1.0016x over previous
#include <cuda_runtime.h>
#include <cuda_bf16.h>
#include <cstdint>

#define BATCH 16
#define T0 64000
#define T1 32000
#define CH1 32
#define T2 16000
#define CH2 64
#define T3 8000
#define CH3 128
#define NH 64
#define NB 64
#define X2R 8072
#define NPB 63      // conv3 blocks per batch = pool partials

typedef unsigned long long ull;

// ---------------- PTX helpers ----------------
__device__ __forceinline__ uint32_t smem_u32(const void* p) {
    uint32_t a;
    asm("{ .reg .u64 t; cvta.to.shared.u64 t, %1; cvt.u32.u64 %0, t; }" : "=r"(a) : "l"(p));
    return a;
}
#define MBAR_INIT(a, n) asm volatile("mbarrier.init.shared.b64 [%0], %1;" :: "r"(a), "r"((uint32_t)(n)) : "memory")
#define MBAR_EXPECT(a, tx) asm volatile("mbarrier.arrive.expect_tx.shared.b64 _, [%0], %1;" :: "r"(a), "r"((uint32_t)(tx)) : "memory")
#define MBAR_ARRIVE(a) asm volatile("mbarrier.arrive.shared.b64 _, [%0];" :: "r"(a) : "memory")
#define MBAR_WAIT(a, ph) do { \
    uint32_t _m = (a), _p = (ph), _d; \
    asm volatile("{ .reg .pred p; mbarrier.try_wait.parity.acquire.cta.shared::cta.b64 p, [%1], %2; selp.b32 %0, 1, 0, p; }" \
        : "=r"(_d) : "r"(_m), "r"(_p) : "memory"); \
    if (!_d) { \
        asm volatile("{ .reg .pred P1; WL_%=: mbarrier.try_wait.parity.acquire.cta.shared::cta.b64 P1, [%0], %1, 0x989680; @P1 bra.uni WD_%=; bra.uni WL_%=; WD_%=: }" \
            :: "r"(_m), "r"(_p) : "memory"); \
    } } while (0)
#define BULK_G2S(dst, src, bytes, mbar) \
    asm volatile("cp.async.bulk.shared::cluster.global.mbarrier::complete_tx::bytes [%0], [%1], %2, [%3];" \
        :: "r"(dst), "l"(src), "r"((uint32_t)(bytes)), "r"(mbar) : "memory")
#define CP16(dst, src) asm volatile("cp.async.cg.shared.global [%0], [%1], 16;" :: "r"(dst), "l"(src))
#define CP_COMMIT() asm volatile("cp.async.commit_group;" ::: "memory")
#define CP_WAIT0() asm volatile("cp.async.wait_group 0;" ::: "memory")

#define LDSM_X4(r, addr) \
    asm volatile("ldmatrix.sync.aligned.m8n8.x4.shared.b16 {%0,%1,%2,%3}, [%4];" \
        : "=r"((r)[0]), "=r"((r)[1]), "=r"((r)[2]), "=r"((r)[3]) : "r"(addr))
#define LDSM_X4_T(r, addr) \
    asm volatile("ldmatrix.sync.aligned.m8n8.x4.trans.shared.b16 {%0,%1,%2,%3}, [%4];" \
        : "=r"((r)[0]), "=r"((r)[1]), "=r"((r)[2]), "=r"((r)[3]) : "r"(addr))
#define MMA16816(d, a, b0, b1) \
    asm volatile("mma.sync.aligned.m16n8k16.row.col.f32.bf16.bf16.f32 " \
        "{%0,%1,%2,%3}, {%4,%5,%6,%7}, {%8,%9}, {%0,%1,%2,%3};" \
        : "+f"((d)[0]), "+f"((d)[1]), "+f"((d)[2]), "+f"((d)[3]) \
        : "r"((a)[0]), "r"((a)[1]), "r"((a)[2]), "r"((a)[3]), "r"(b0), "r"(b1))

// packed f32x2 via fma only
__device__ __forceinline__ ull fma2(ull a, ull b, ull c) {
    ull d;
    asm("fma.rn.f32x2 %0, %1, %2, %3;" : "=l"(d) : "l"(a), "l"(b), "l"(c));
    return d;
}
__device__ __forceinline__ ull pk2(float x, float y) {
    return (ull)(unsigned)__float_as_int(x) | ((ull)(unsigned)__float_as_int(y) << 32);
}

// ---------------- scratch ----------------
__device__ __nv_bfloat16 g_x2e[(size_t)BATCH * X2R * CH2];
__device__ __nv_bfloat16 g_x2o[(size_t)BATCH * X2R * CH2];
__device__ __nv_bfloat16 g_w2s[18 * 32 * 72];
__device__ __nv_bfloat16 g_w3s[18 * 64 * 136];
__device__ float g_poolpart[BATCH * NPB * CH3];
__device__ float g_amps[BATCH * NH];
__device__ float g_nmag[BATCH * NB];

// ---------------- prep ----------------
__global__ void prep_kernel(const float* __restrict__ w2, const float* __restrict__ w3) {
    int tid = blockIdx.x * blockDim.x + threadIdx.x;
    int stride = gridDim.x * blockDim.x;
    for (int i = tid; i < 18 * 32 * 64; i += stride) {
        int co = i & 63, ci = (i >> 6) & 31, tp = i >> 11;
        int k = tp >> 1, p = tp & 1;
        float w = w2[(co * CH1 + ci) * 9 + k];
        __nv_bfloat16 h = __float2bfloat16_rn(w);
        __nv_bfloat16 v = p ? __float2bfloat16_rn(w - __bfloat162float(h)) : h;
        g_w2s[(tp * 32 + ci) * 72 + co] = v;
    }
    for (int i = tid; i < 18 * 64 * 128; i += stride) {
        int co = i & 127, ci = (i >> 7) & 63, tp = i >> 13;
        int k = tp >> 1, p = tp & 1;
        float w = w3[(co * CH2 + ci) * 9 + k];
        __nv_bfloat16 h = __float2bfloat16_rn(w);
        __nv_bfloat16 v = p ? __float2bfloat16_rn(w - __bfloat162float(h)) : h;
        g_w3s[(tp * 64 + ci) * 136 + co] = v;
    }
}

// ---------------- conv2 (fused conv1 prologue), weights STREAMED (4-stage ring) ----------------
// smem: [0,64) mbars | audio 1048 f32 @64 | A even 260x80 @4352 | A odd | ring 4 x 4608
#define C2_SAUD 64
#define C2_AROWS 260
#define C2_SAE 4352
#define C2_SAO (C2_SAE + C2_AROWS * 80)
#define C2_SW  (C2_SAO + C2_AROWS * 80)
#define C2_WSTG 4608
#define C2_SMEM (C2_SW + 4 * C2_WSTG)
__global__ __launch_bounds__(256) void conv2_mma(const float* __restrict__ audio,
                                                 const float* __restrict__ w1,
                                                 const float* __restrict__ b1,
                                                 const float* __restrict__ b2v) {
    extern __shared__ char smem[];
    uint32_t sb = smem_u32(smem);
    float* s_a = reinterpret_cast<float*>(smem + C2_SAUD);
    int tid = threadIdx.x;
    int b = blockIdx.y;
    int t0 = blockIdx.x * 256;
    // barriers: rdy[s] at sb + 8*s, empty[s] at sb + 32 + 8*s
    if (tid == 0) {
        for (int s = 0; s < 4; s++) { MBAR_INIT(sb + 8 * s, 1); MBAR_INIT(sb + 32 + 8 * s, 256); }
    }
    __syncthreads();
    if (tid == 0) {
        for (int s = 0; s < 4; s++) {
            MBAR_EXPECT(sb + 8 * s, C2_WSTG);
            BULK_G2S(sb + C2_SW + s * C2_WSTG, (const char*)g_w2s + s * (size_t)C2_WSTG, C2_WSTG, sb + 8 * s);
        }
    }
    // ---- audio tile: s_a[j] = audio[4*t0 - 12 + j], j in [0,1048) ----
    {
        const float* ab = audio + (size_t)b * T0;
        int gbase = 4 * t0 - 12;
        for (int j = tid; j < 1048; j += 256) {
            int gi = gbase + j;
            s_a[j] = (gi >= 0 && gi < T0) ? ab[gi] : 0.0f;
        }
    }
    __syncthreads();
    // ---- fused conv1: t1[u], u = 2*t0-4 .. 2*t0+515 -> bf16 A tiles (round-8 verified) ----
    {
        int ci = tid & 31;
        float w[9];
#pragma unroll
        for (int k = 0; k < 9; k++) w[k] = __ldg(w1 + ci * 9 + k);
        float bias = __ldg(b1 + ci);
        for (int ul = tid >> 5; ul < 520; ul += 8) {
            int u = 2 * t0 - 4 + ul;
            float acc = bias;
#pragma unroll
            for (int k = 0; k < 9; k++) acc = fmaf(w[k], s_a[2 * ul + k], acc);
            float v = (u >= 0 && u < T1) ? fmaxf(acc, 0.0f) : 0.0f;
            __nv_bfloat16 bv = __float2bfloat16_rn(v);
            if (ul & 1) {
                int i = (ul - 1) >> 1;
                *reinterpret_cast<__nv_bfloat16*>(smem + C2_SAO + i * 80 + ci * 2) = bv;
            } else {
                int i = ul >> 1;
                *reinterpret_cast<__nv_bfloat16*>(smem + C2_SAE + i * 80 + ci * 2) = bv;
            }
        }
    }
    __syncthreads();

    int lane = tid & 31, w = tid >> 5;
    int gid = lane >> 2, tig = lane & 3;
    float d[2][8][4];
#pragma unroll
    for (int i = 0; i < 2; i++)
#pragma unroll
        for (int j = 0; j < 8; j++)
#pragma unroll
            for (int q = 0; q < 4; q++) d[i][j][q] = 0.0f;

    for (int tp = 0; tp < 18; tp++) {
        int s = tp & 3;
        MBAR_WAIT(sb + 8 * s, (tp >> 2) & 1);
        int k = tp >> 1;
        int par = k & 1;
        int j0 = par ? ((k - 5) / 2 + 2) : ((k - 4) / 2 + 2);
        uint32_t abase = sb + (par ? C2_SAO : C2_SAE);
        uint32_t wtile = sb + C2_SW + s * C2_WSTG;
        uint32_t bb[2][4][4];
#pragma unroll
        for (int ks = 0; ks < 2; ks++)
#pragma unroll
            for (int nb2 = 0; nb2 < 4; nb2++) {
                uint32_t addr = wtile + (ks * 16 + (lane & 15)) * 144 + (nb2 * 16 + (lane >> 4) * 8) * 2;
                LDSM_X4_T(bb[ks][nb2], addr);
            }
#pragma unroll
        for (int ms = 0; ms < 2; ms++) {
            int mrow = w * 32 + ms * 16 + j0;
            uint32_t a[2][4];
#pragma unroll
            for (int ks = 0; ks < 2; ks++) {
                uint32_t addr = abase + (mrow + (lane & 15)) * 80 + (ks * 16 + (lane >> 4) * 8) * 2;
                LDSM_X4(a[ks], addr);
            }
#pragma unroll
            for (int ks = 0; ks < 2; ks++)
#pragma unroll
                for (int nb2 = 0; nb2 < 4; nb2++) {
                    MMA16816(d[ms][nb2 * 2],     a[ks], bb[ks][nb2][0], bb[ks][nb2][1]);
                    MMA16816(d[ms][nb2 * 2 + 1], a[ks], bb[ks][nb2][2], bb[ks][nb2][3]);
                }
        }
        MBAR_ARRIVE(sb + 32 + 8 * s);
        if (tid == 0 && tp + 4 < 18) {
            MBAR_WAIT(sb + 32 + 8 * s, (tp >> 2) & 1);
            MBAR_EXPECT(sb + 8 * s, C2_WSTG);
            BULK_G2S(sb + C2_SW + s * C2_WSTG, (const char*)g_w2s + (tp + 4) * (size_t)C2_WSTG, C2_WSTG, sb + 8 * s);
        }
    }
#pragma unroll
    for (int ms = 0; ms < 2; ms++)
#pragma unroll
        for (int nb = 0; nb < 8; nb++) {
            int co = nb * 8 + tig * 2;
            float2 bias = *reinterpret_cast<const float2*>(b2v + co);
#pragma unroll
            for (int half = 0; half < 2; half++) {
                int t = t0 + w * 32 + ms * 16 + gid + half * 8;
                if (t < T2) {
                    float v0 = fmaxf(d[ms][nb][half * 2]     + bias.x, 0.0f);
                    float v1 = fmaxf(d[ms][nb][half * 2 + 1] + bias.y, 0.0f);
                    __nv_bfloat162 pv;
                    pv.x = __float2bfloat16_rn(v0);
                    pv.y = __float2bfloat16_rn(v1);
                    size_t idx = ((size_t)b * X2R + (t >> 1) + 4) * CH2 + co;
                    if (t & 1) *reinterpret_cast<__nv_bfloat162*>(&g_x2o[idx]) = pv;
                    else       *reinterpret_cast<__nv_bfloat162*>(&g_x2e[idx]) = pv;
                }
            }
        }
}

// ---------------- conv3: HMMA 2Mx4N warps, fused mean-pool epilogue ----------------
#define C3_AROWS 132
#define C3_SAE 2048
#define C3_SAO (2048 + C3_AROWS * 144)
#define C3_SW  (2048 + 2 * C3_AROWS * 144)
#define C3_WSTG 17408
#define C3_SMEM (C3_SW + 4 * C3_WSTG)
__global__ __launch_bounds__(256) void conv3_mma(const float* __restrict__ b3v) {
    extern __shared__ char smem[];
    uint32_t sb = smem_u32(smem);
    float* spool = reinterpret_cast<float*>(smem + 1024);
    int tid = threadIdx.x;
    int b = blockIdx.y;
    int t0 = blockIdx.x * 128;
    if (tid == 0) {
        for (int s = 0; s < 4; s++) { MBAR_INIT(sb + 8 * s, 1); MBAR_INIT(sb + 32 + 8 * s, 256); }
    }
    __syncthreads();
    if (tid == 0) {
        for (int s = 0; s < 4; s++) {
            MBAR_EXPECT(sb + 8 * s, C3_WSTG);
            BULK_G2S(sb + C3_SW + s * C3_WSTG, (const char*)g_w3s + s * (size_t)C3_WSTG, C3_WSTG, sb + 8 * s);
        }
    }
    for (int c = tid; c < C3_AROWS * 8; c += 256) {
        int row = c >> 3, part = c & 7;
        size_t so = (((size_t)b * X2R + t0 + 2 + row) * 64 + part * 8) * 2;
        CP16(sb + C3_SAE + row * 144 + part * 16, (const char*)g_x2e + so);
        CP16(sb + C3_SAO + row * 144 + part * 16, (const char*)g_x2o + so);
    }
    CP_COMMIT();
    CP_WAIT0();
    __syncthreads();

    int lane = tid & 31, w = tid >> 5;
    int wm = w >> 2, wn = w & 3;
    int gid = lane >> 2, tig = lane & 3;
    float d[4][4][4];
#pragma unroll
    for (int i = 0; i < 4; i++)
#pragma unroll
        for (int j = 0; j < 4; j++)
#pragma unroll
            for (int q = 0; q < 4; q++) d[i][j][q] = 0.0f;

    for (int tp = 0; tp < 18; tp++) {
        int s = tp & 3;
        MBAR_WAIT(sb + 8 * s, (tp >> 2) & 1);
        int k = tp >> 1;
        int par = k & 1;
        int j0 = par ? ((k - 5) / 2 + 2) : ((k - 4) / 2 + 2);
        uint32_t abase = sb + (par ? C3_SAO : C3_SAE);
        uint32_t wtile = sb + C3_SW + s * C3_WSTG;
        uint32_t bb[2][4][4];
#pragma unroll
        for (int nbl = 0; nbl < 2; nbl++)
#pragma unroll
            for (int ks = 0; ks < 4; ks++) {
                uint32_t addr = wtile + (ks * 16 + (lane & 15)) * 272
                              + (wn * 32 + nbl * 16 + (lane >> 4) * 8) * 2;
                LDSM_X4_T(bb[nbl][ks], addr);
            }
#pragma unroll
        for (int ms = 0; ms < 4; ms++) {
            int mrow = wm * 64 + ms * 16 + j0;
            uint32_t a[4][4];
#pragma unroll
            for (int ks = 0; ks < 4; ks++) {
                uint32_t addr = abase + (mrow + (lane & 15)) * 144 + (ks * 16 + (lane >> 4) * 8) * 2;
                LDSM_X4(a[ks], addr);
            }
#pragma unroll
            for (int nbl = 0; nbl < 2; nbl++)
#pragma unroll
                for (int ks = 0; ks < 4; ks++) {
                    MMA16816(d[ms][nbl * 2],     a[ks], bb[nbl][ks][0], bb[nbl][ks][1]);
                    MMA16816(d[ms][nbl * 2 + 1], a[ks], bb[nbl][ks][2], bb[nbl][ks][3]);
                }
        }
        MBAR_ARRIVE(sb + 32 + 8 * s);
        if (tid == 0 && tp + 4 < 18) {
            MBAR_WAIT(sb + 32 + 8 * s, (tp >> 2) & 1);
            MBAR_EXPECT(sb + 8 * s, C3_WSTG);
            BULK_G2S(sb + C3_SW + s * C3_WSTG, (const char*)g_w3s + (tp + 4) * (size_t)C3_WSTG, C3_WSTG, sb + 8 * s);
        }
    }

    float psx[4], psy[4];
#pragma unroll
    for (int nb = 0; nb < 4; nb++) {
        int co = wn * 32 + nb * 8 + tig * 2;
        float2 bias = *reinterpret_cast<const float2*>(b3v + co);
        float sx = 0.0f, sy = 0.0f;
#pragma unroll
        for (int ms = 0; ms < 4; ms++)
#pragma unroll
            for (int hz = 0; hz < 2; hz++) {
                int t = t0 + wm * 64 + ms * 16 + gid + hz * 8;
                if (t < T3) {
                    sx += fmaxf(d[ms][nb][hz * 2]     + bias.x, 0.0f);
                    sy += fmaxf(d[ms][nb][hz * 2 + 1] + bias.y, 0.0f);
                }
            }
        psx[nb] = sx; psy[nb] = sy;
    }
#pragma unroll
    for (int off = 4; off < 32; off <<= 1)
#pragma unroll
        for (int nb = 0; nb < 4; nb++) {
            psx[nb] += __shfl_xor_sync(0xffffffffu, psx[nb], off);
            psy[nb] += __shfl_xor_sync(0xffffffffu, psy[nb], off);
        }
    if (lane < 4) {
#pragma unroll
        for (int nb = 0; nb < 4; nb++) {
            int co = wn * 32 + nb * 8 + lane * 2;
            spool[wm * 128 + co]     = psx[nb];
            spool[wm * 128 + co + 1] = psy[nb];
        }
    }
    __syncthreads();
    if (tid < 128)
        g_poolpart[(b * NPB + blockIdx.x) * CH3 + tid] = spool[tid] + spool[128 + tid];
}

// ---------------- head ----------------
__global__ void head_kernel(const float* __restrict__ wl, const float* __restrict__ bl) {
    __shared__ float sp[128];
    __shared__ float s_amp[64];
    __shared__ float s_sum;
    int b = blockIdx.x, j = threadIdx.x;
    float s = 0.0f;
    for (int p = 0; p < NPB; p++) s += g_poolpart[(b * NPB + p) * CH3 + j];
    sp[j] = s * (1.0f / 8000.0f);
    __syncthreads();
    float dot = __ldg(bl + j);
    for (int c = 0; c < 128; c++) dot = fmaf(sp[c], __ldg(wl + j * 128 + c), dot);
    if (j < 64) s_amp[j] = fmaxf(dot, 0.0f);
    __syncthreads();
    if (j == 0) {
        float t = 0.0f;
        for (int h = 0; h < 64; h++) t += s_amp[h];
        s_sum = t + 1e-6f;
    }
    __syncthreads();
    if (j < 64) g_amps[b * 64 + j] = s_amp[j] / s_sum;
    else        g_nmag[b * 64 + (j - 64)] = dot;
}

// ---------------- synth: packed f32x2 harmonic pairs ----------------
__global__ __launch_bounds__(256) void synth_kernel(const float* __restrict__ f0,
                                                    const float* __restrict__ wn,
                                                    float* __restrict__ out) {
    __shared__ __align__(16) float s_amps[64];
    __shared__ float s_nm[64];
    int b = blockIdx.y;
    if (threadIdx.x < 64)       s_amps[threadIdx.x]    = g_amps[b * 64 + threadIdx.x];
    else if (threadIdx.x < 128) s_nm[threadIdx.x - 64] = g_nmag[b * 64 + threadIdx.x - 64];
    __syncthreads();
    int t = blockIdx.x * 256 + threadIdx.x;

    constexpr float DELTA  = 4.0f / 63999.0f;
    constexpr float TWO_PI = 6.283185307179586f;
    float tf  = (float)t * DELTA;
    float a   = TWO_PI * f0[(size_t)b * T0 + t];

    constexpr double PIO2_D = 1.5707963267948966192313216916397514;
    constexpr float RC1 = (float)PIO2_D;
    constexpr float RC2 = (float)(PIO2_D - (double)RC1);
    constexpr float INV_PIO2 = 0.63661977236758134308f;
    constexpr float MAGIC = 12582912.0f;

    const ull ONE2   = pk2(1.0f, 1.0f);
    const ull ZERO2  = 0ULL;
    const ull INV2   = pk2(INV_PIO2, INV_PIO2);
    const ull MAG2   = pk2(MAGIC, MAGIC);
    const ull NMAG2  = pk2(-MAGIC, -MAGIC);
    const ull NRC1_2 = pk2(-RC1, -RC1);
    const ull NRC2_2 = pk2(-RC2, -RC2);
    const ull SC1_2  = pk2(-1.9515295891e-4f, -1.9515295891e-4f);
    const ull SC2_2  = pk2(8.3321608736e-3f,  8.3321608736e-3f);
    const ull SC3_2  = pk2(-1.6666654611e-1f, -1.6666654611e-1f);
    const ull CC1_2  = pk2(2.443315711809948e-5f,  2.443315711809948e-5f);
    const ull CC2_2  = pk2(-1.388731625493765e-3f, -1.388731625493765e-3f);
    const ull CC3_2  = pk2(4.166664568298827e-2f,  4.166664568298827e-2f);
    const ull NHALF2 = pk2(-0.5f, -0.5f);
    const ull TWO2   = pk2(2.0f, 2.0f);

    ull a2  = pk2(a, a);
    ull tf2 = pk2(tf, tf);
    ull h2  = pk2(1.0f, 2.0f);
    ull acc2 = ZERO2;
    const ull* amps2 = reinterpret_cast<const ull*>(s_amps);

#pragma unroll
    for (int p = 0; p < 32; p++) {
        ull bh2 = fma2(a2, h2, ZERO2);
        ull x2  = fma2(bh2, tf2, ZERO2);
        ull kr2 = fma2(x2, INV2, MAG2);
        unsigned q0 = (unsigned)kr2, q1 = (unsigned)(kr2 >> 32);
        ull kf2 = fma2(kr2, ONE2, NMAG2);
        ull r2  = fma2(kf2, NRC1_2, x2);
        r2      = fma2(kf2, NRC2_2, r2);
        ull z2  = fma2(r2, r2, ZERO2);
        ull ps2 = fma2(SC1_2, z2, SC2_2);
        ps2     = fma2(ps2, z2, SC3_2);
        ps2     = fma2(ps2, z2, ZERO2);
        ull sr2 = fma2(ps2, r2, r2);
        ull pc2 = fma2(CC1_2, z2, CC2_2);
        pc2     = fma2(pc2, z2, CC3_2);
        pc2     = fma2(pc2, z2, NHALF2);
        ull cr2 = fma2(pc2, z2, ONE2);
        unsigned s0 = (unsigned)sr2, s1 = (unsigned)(sr2 >> 32);
        unsigned c0 = (unsigned)cr2, c1 = (unsigned)(cr2 >> 32);
        unsigned v0 = (q0 & 1u) ? c0 : s0;  v0 ^= (q0 << 30) & 0x80000000u;
        unsigned v1 = (q1 & 1u) ? c1 : s1;  v1 ^= (q1 << 30) & 0x80000000u;
        ull v2 = (ull)v0 | ((ull)v1 << 32);
        acc2 = fma2(amps2[p], v2, acc2);
        h2 = fma2(h2, ONE2, TWO2);
    }
    float acc = __int_as_float((int)(unsigned)acc2)
              + __int_as_float((int)(unsigned)(acc2 >> 32));

    int bin = t / 1000;
    float shaped = wn[(size_t)b * T0 + t] * s_nm[bin];
    out[(size_t)b * T0 + t] = acc + shaped;
}

extern "C" void kernel_launch(void* const* d_in, const int* in_sizes, int n_in,
                              void* d_out, int out_size) {
    (void)in_sizes; (void)n_in; (void)out_size;
    const float* audio = (const float*)d_in[0];
    const float* f0    = (const float*)d_in[1];
    const float* wn    = (const float*)d_in[2];
    const float* w1    = (const float*)d_in[3];
    const float* b1    = (const float*)d_in[4];
    const float* w2    = (const float*)d_in[5];
    const float* b2    = (const float*)d_in[6];
    const float* w3    = (const float*)d_in[7];
    const float* b3    = (const float*)d_in[8];
    const float* wl    = (const float*)d_in[9];
    const float* bl    = (const float*)d_in[10];
    float* out = (float*)d_out;

    cudaFuncSetAttribute(conv2_mma, cudaFuncAttributeMaxDynamicSharedMemorySize, C2_SMEM);
    cudaFuncSetAttribute(conv3_mma, cudaFuncAttributeMaxDynamicSharedMemorySize, C3_SMEM);

    prep_kernel<<<64, 256>>>(w2, w3);
    conv2_mma<<<dim3(63, 16), 256, C2_SMEM>>>(audio, w1, b1, b2);
    conv3_mma<<<dim3(63, 16), 256, C3_SMEM>>>(b3);
    head_kernel<<<16, 128>>>(wl, bl);
    synth_kernel<<<dim3(250, 16), 256>>>(f0, wn, out);
}

// round 17
// speedup vs baseline: 1.0825x; 1.0243x over previous
#include <cuda_runtime.h>
#include <cuda_bf16.h>
#include <cstdint>

#define BATCH 16
#define T0 64000
#define T1 32000
#define CH1 32
#define T2 16000
#define CH2 64
#define T3 8000
#define CH3 128
#define NH 64
#define NB 64
#define X2R 8072
#define NPB 63      // conv3 blocks per batch = pool partials

typedef unsigned long long ull;

// ---------------- PTX helpers ----------------
__device__ __forceinline__ uint32_t smem_u32(const void* p) {
    uint32_t a;
    asm("{ .reg .u64 t; cvta.to.shared.u64 t, %1; cvt.u32.u64 %0, t; }" : "=r"(a) : "l"(p));
    return a;
}
#define MBAR_INIT(a, n) asm volatile("mbarrier.init.shared.b64 [%0], %1;" :: "r"(a), "r"((uint32_t)(n)) : "memory")
#define MBAR_EXPECT(a, tx) asm volatile("mbarrier.arrive.expect_tx.shared.b64 _, [%0], %1;" :: "r"(a), "r"((uint32_t)(tx)) : "memory")
#define MBAR_ARRIVE(a) asm volatile("mbarrier.arrive.shared.b64 _, [%0];" :: "r"(a) : "memory")
#define MBAR_WAIT(a, ph) do { \
    uint32_t _m = (a), _p = (ph), _d; \
    asm volatile("{ .reg .pred p; mbarrier.try_wait.parity.acquire.cta.shared::cta.b64 p, [%1], %2; selp.b32 %0, 1, 0, p; }" \
        : "=r"(_d) : "r"(_m), "r"(_p) : "memory"); \
    if (!_d) { \
        asm volatile("{ .reg .pred P1; WL_%=: mbarrier.try_wait.parity.acquire.cta.shared::cta.b64 P1, [%0], %1, 0x989680; @P1 bra.uni WD_%=; bra.uni WL_%=; WD_%=: }" \
            :: "r"(_m), "r"(_p) : "memory"); \
    } } while (0)
#define BULK_G2S(dst, src, bytes, mbar) \
    asm volatile("cp.async.bulk.shared::cluster.global.mbarrier::complete_tx::bytes [%0], [%1], %2, [%3];" \
        :: "r"(dst), "l"(src), "r"((uint32_t)(bytes)), "r"(mbar) : "memory")
#define CP16(dst, src) asm volatile("cp.async.cg.shared.global [%0], [%1], 16;" :: "r"(dst), "l"(src))
#define CP_COMMIT() asm volatile("cp.async.commit_group;" ::: "memory")
#define CP_WAIT0() asm volatile("cp.async.wait_group 0;" ::: "memory")

#define LDSM_X4(r, addr) \
    asm volatile("ldmatrix.sync.aligned.m8n8.x4.shared.b16 {%0,%1,%2,%3}, [%4];" \
        : "=r"((r)[0]), "=r"((r)[1]), "=r"((r)[2]), "=r"((r)[3]) : "r"(addr))
#define LDSM_X4_T(r, addr) \
    asm volatile("ldmatrix.sync.aligned.m8n8.x4.trans.shared.b16 {%0,%1,%2,%3}, [%4];" \
        : "=r"((r)[0]), "=r"((r)[1]), "=r"((r)[2]), "=r"((r)[3]) : "r"(addr))
#define MMA16816(d, a, b0, b1) \
    asm volatile("mma.sync.aligned.m16n8k16.row.col.f32.bf16.bf16.f32 " \
        "{%0,%1,%2,%3}, {%4,%5,%6,%7}, {%8,%9}, {%0,%1,%2,%3};" \
        : "+f"((d)[0]), "+f"((d)[1]), "+f"((d)[2]), "+f"((d)[3]) \
        : "r"((a)[0]), "r"((a)[1]), "r"((a)[2]), "r"((a)[3]), "r"(b0), "r"(b1))

// packed f32x2 via fma only
__device__ __forceinline__ ull fma2(ull a, ull b, ull c) {
    ull d;
    asm("fma.rn.f32x2 %0, %1, %2, %3;" : "=l"(d) : "l"(a), "l"(b), "l"(c));
    return d;
}
__device__ __forceinline__ ull pk2(float x, float y) {
    return (ull)(unsigned)__float_as_int(x) | ((ull)(unsigned)__float_as_int(y) << 32);
}

// ---------------- scratch ----------------
__device__ __nv_bfloat16 g_x2e[(size_t)BATCH * X2R * CH2];
__device__ __nv_bfloat16 g_x2o[(size_t)BATCH * X2R * CH2];
__device__ __nv_bfloat16 g_w2s[18 * 32 * 72];
__device__ __nv_bfloat16 g_w3s[18 * 64 * 136];
__device__ float g_wlt[128 * 128];   // wl transposed: [c][j]
__device__ float g_poolpart[BATCH * NPB * CH3];
__device__ float g_amps[BATCH * NH];
__device__ float g_nmag[BATCH * NB];

// ---------------- prep ----------------
__global__ void prep_kernel(const float* __restrict__ w2, const float* __restrict__ w3,
                            const float* __restrict__ wl) {
    int tid = blockIdx.x * blockDim.x + threadIdx.x;
    int stride = gridDim.x * blockDim.x;
    for (int i = tid; i < 18 * 32 * 64; i += stride) {
        int co = i & 63, ci = (i >> 6) & 31, tp = i >> 11;
        int k = tp >> 1, p = tp & 1;
        float w = w2[(co * CH1 + ci) * 9 + k];
        __nv_bfloat16 h = __float2bfloat16_rn(w);
        __nv_bfloat16 v = p ? __float2bfloat16_rn(w - __bfloat162float(h)) : h;
        g_w2s[(tp * 32 + ci) * 72 + co] = v;
    }
    for (int i = tid; i < 18 * 64 * 128; i += stride) {
        int co = i & 127, ci = (i >> 7) & 63, tp = i >> 13;
        int k = tp >> 1, p = tp & 1;
        float w = w3[(co * CH2 + ci) * 9 + k];
        __nv_bfloat16 h = __float2bfloat16_rn(w);
        __nv_bfloat16 v = p ? __float2bfloat16_rn(w - __bfloat162float(h)) : h;
        g_w3s[(tp * 64 + ci) * 136 + co] = v;
    }
    // transpose wl (row j, col c) -> g_wlt[c*128 + j] for coalesced head GEMV
    for (int i = tid; i < 128 * 128; i += stride) {
        int j = i >> 7, c = i & 127;
        g_wlt[c * 128 + j] = wl[j * 128 + c];
    }
}

// ---------------- conv2 (fused conv1 prologue), weights STREAMED (4-stage ring) ----------------
// smem: [0,64) mbars | audio 1048 f32 @64 | A even 260x80 @4352 | A odd | ring 4 x 4608
#define C2_SAUD 64
#define C2_AROWS 260
#define C2_SAE 4352
#define C2_SAO (C2_SAE + C2_AROWS * 80)
#define C2_SW  (C2_SAO + C2_AROWS * 80)
#define C2_WSTG 4608
#define C2_SMEM (C2_SW + 4 * C2_WSTG)
__global__ __launch_bounds__(256) void conv2_mma(const float* __restrict__ audio,
                                                 const float* __restrict__ w1,
                                                 const float* __restrict__ b1,
                                                 const float* __restrict__ b2v) {
    extern __shared__ char smem[];
    uint32_t sb = smem_u32(smem);
    float* s_a = reinterpret_cast<float*>(smem + C2_SAUD);
    int tid = threadIdx.x;
    int b = blockIdx.y;
    int t0 = blockIdx.x * 256;
    if (tid == 0) {
        for (int s = 0; s < 4; s++) { MBAR_INIT(sb + 8 * s, 1); MBAR_INIT(sb + 32 + 8 * s, 256); }
    }
    __syncthreads();
    if (tid == 0) {
        for (int s = 0; s < 4; s++) {
            MBAR_EXPECT(sb + 8 * s, C2_WSTG);
            BULK_G2S(sb + C2_SW + s * C2_WSTG, (const char*)g_w2s + s * (size_t)C2_WSTG, C2_WSTG, sb + 8 * s);
        }
    }
    // ---- audio tile: s_a[j] = audio[4*t0 - 12 + j], j in [0,1048) ----
    {
        const float* ab = audio + (size_t)b * T0;
        int gbase = 4 * t0 - 12;
        for (int j = tid; j < 1048; j += 256) {
            int gi = gbase + j;
            s_a[j] = (gi >= 0 && gi < T0) ? ab[gi] : 0.0f;
        }
    }
    __syncthreads();
    // ---- fused conv1: t1[u], u = 2*t0-4 .. 2*t0+515 -> bf16 A tiles ----
    {
        int ci = tid & 31;
        float w[9];
#pragma unroll
        for (int k = 0; k < 9; k++) w[k] = __ldg(w1 + ci * 9 + k);
        float bias = __ldg(b1 + ci);
        for (int ul = tid >> 5; ul < 520; ul += 8) {
            int u = 2 * t0 - 4 + ul;
            float acc = bias;
#pragma unroll
            for (int k = 0; k < 9; k++) acc = fmaf(w[k], s_a[2 * ul + k], acc);
            float v = (u >= 0 && u < T1) ? fmaxf(acc, 0.0f) : 0.0f;
            __nv_bfloat16 bv = __float2bfloat16_rn(v);
            if (ul & 1) {
                int i = (ul - 1) >> 1;
                *reinterpret_cast<__nv_bfloat16*>(smem + C2_SAO + i * 80 + ci * 2) = bv;
            } else {
                int i = ul >> 1;
                *reinterpret_cast<__nv_bfloat16*>(smem + C2_SAE + i * 80 + ci * 2) = bv;
            }
        }
    }
    __syncthreads();

    int lane = tid & 31, w = tid >> 5;
    int gid = lane >> 2, tig = lane & 3;
    float d[2][8][4];
#pragma unroll
    for (int i = 0; i < 2; i++)
#pragma unroll
        for (int j = 0; j < 8; j++)
#pragma unroll
            for (int q = 0; q < 4; q++) d[i][j][q] = 0.0f;

    for (int tp = 0; tp < 18; tp++) {
        int s = tp & 3;
        MBAR_WAIT(sb + 8 * s, (tp >> 2) & 1);
        int k = tp >> 1;
        int par = k & 1;
        int j0 = par ? ((k - 5) / 2 + 2) : ((k - 4) / 2 + 2);
        uint32_t abase = sb + (par ? C2_SAO : C2_SAE);
        uint32_t wtile = sb + C2_SW + s * C2_WSTG;
        uint32_t bb[2][4][4];
#pragma unroll
        for (int ks = 0; ks < 2; ks++)
#pragma unroll
            for (int nb2 = 0; nb2 < 4; nb2++) {
                uint32_t addr = wtile + (ks * 16 + (lane & 15)) * 144 + (nb2 * 16 + (lane >> 4) * 8) * 2;
                LDSM_X4_T(bb[ks][nb2], addr);
            }
#pragma unroll
        for (int ms = 0; ms < 2; ms++) {
            int mrow = w * 32 + ms * 16 + j0;
            uint32_t a[2][4];
#pragma unroll
            for (int ks = 0; ks < 2; ks++) {
                uint32_t addr = abase + (mrow + (lane & 15)) * 80 + (ks * 16 + (lane >> 4) * 8) * 2;
                LDSM_X4(a[ks], addr);
            }
#pragma unroll
            for (int ks = 0; ks < 2; ks++)
#pragma unroll
                for (int nb2 = 0; nb2 < 4; nb2++) {
                    MMA16816(d[ms][nb2 * 2],     a[ks], bb[ks][nb2][0], bb[ks][nb2][1]);
                    MMA16816(d[ms][nb2 * 2 + 1], a[ks], bb[ks][nb2][2], bb[ks][nb2][3]);
                }
        }
        MBAR_ARRIVE(sb + 32 + 8 * s);
        if (tid == 0 && tp + 4 < 18) {
            MBAR_WAIT(sb + 32 + 8 * s, (tp >> 2) & 1);
            MBAR_EXPECT(sb + 8 * s, C2_WSTG);
            BULK_G2S(sb + C2_SW + s * C2_WSTG, (const char*)g_w2s + (tp + 4) * (size_t)C2_WSTG, C2_WSTG, sb + 8 * s);
        }
    }
#pragma unroll
    for (int ms = 0; ms < 2; ms++)
#pragma unroll
        for (int nb = 0; nb < 8; nb++) {
            int co = nb * 8 + tig * 2;
            float2 bias = *reinterpret_cast<const float2*>(b2v + co);
#pragma unroll
            for (int half = 0; half < 2; half++) {
                int t = t0 + w * 32 + ms * 16 + gid + half * 8;
                if (t < T2) {
                    float v0 = fmaxf(d[ms][nb][half * 2]     + bias.x, 0.0f);
                    float v1 = fmaxf(d[ms][nb][half * 2 + 1] + bias.y, 0.0f);
                    __nv_bfloat162 pv;
                    pv.x = __float2bfloat16_rn(v0);
                    pv.y = __float2bfloat16_rn(v1);
                    size_t idx = ((size_t)b * X2R + (t >> 1) + 4) * CH2 + co;
                    if (t & 1) *reinterpret_cast<__nv_bfloat162*>(&g_x2o[idx]) = pv;
                    else       *reinterpret_cast<__nv_bfloat162*>(&g_x2e[idx]) = pv;
                }
            }
        }
}

// ---------------- conv3: HMMA 2Mx4N warps, fused mean-pool epilogue ----------------
#define C3_AROWS 132
#define C3_SAE 2048
#define C3_SAO (2048 + C3_AROWS * 144)
#define C3_SW  (2048 + 2 * C3_AROWS * 144)
#define C3_WSTG 17408
#define C3_SMEM (C3_SW + 4 * C3_WSTG)
__global__ __launch_bounds__(256) void conv3_mma(const float* __restrict__ b3v) {
    extern __shared__ char smem[];
    uint32_t sb = smem_u32(smem);
    float* spool = reinterpret_cast<float*>(smem + 1024);
    int tid = threadIdx.x;
    int b = blockIdx.y;
    int t0 = blockIdx.x * 128;
    if (tid == 0) {
        for (int s = 0; s < 4; s++) { MBAR_INIT(sb + 8 * s, 1); MBAR_INIT(sb + 32 + 8 * s, 256); }
    }
    __syncthreads();
    if (tid == 0) {
        for (int s = 0; s < 4; s++) {
            MBAR_EXPECT(sb + 8 * s, C3_WSTG);
            BULK_G2S(sb + C3_SW + s * C3_WSTG, (const char*)g_w3s + s * (size_t)C3_WSTG, C3_WSTG, sb + 8 * s);
        }
    }
    for (int c = tid; c < C3_AROWS * 8; c += 256) {
        int row = c >> 3, part = c & 7;
        size_t so = (((size_t)b * X2R + t0 + 2 + row) * 64 + part * 8) * 2;
        CP16(sb + C3_SAE + row * 144 + part * 16, (const char*)g_x2e + so);
        CP16(sb + C3_SAO + row * 144 + part * 16, (const char*)g_x2o + so);
    }
    CP_COMMIT();
    CP_WAIT0();
    __syncthreads();

    int lane = tid & 31, w = tid >> 5;
    int wm = w >> 2, wn = w & 3;
    int gid = lane >> 2, tig = lane & 3;
    float d[4][4][4];
#pragma unroll
    for (int i = 0; i < 4; i++)
#pragma unroll
        for (int j = 0; j < 4; j++)
#pragma unroll
            for (int q = 0; q < 4; q++) d[i][j][q] = 0.0f;

    for (int tp = 0; tp < 18; tp++) {
        int s = tp & 3;
        MBAR_WAIT(sb + 8 * s, (tp >> 2) & 1);
        int k = tp >> 1;
        int par = k & 1;
        int j0 = par ? ((k - 5) / 2 + 2) : ((k - 4) / 2 + 2);
        uint32_t abase = sb + (par ? C3_SAO : C3_SAE);
        uint32_t wtile = sb + C3_SW + s * C3_WSTG;
        uint32_t bb[2][4][4];
#pragma unroll
        for (int nbl = 0; nbl < 2; nbl++)
#pragma unroll
            for (int ks = 0; ks < 4; ks++) {
                uint32_t addr = wtile + (ks * 16 + (lane & 15)) * 272
                              + (wn * 32 + nbl * 16 + (lane >> 4) * 8) * 2;
                LDSM_X4_T(bb[nbl][ks], addr);
            }
#pragma unroll
        for (int ms = 0; ms < 4; ms++) {
            int mrow = wm * 64 + ms * 16 + j0;
            uint32_t a[4][4];
#pragma unroll
            for (int ks = 0; ks < 4; ks++) {
                uint32_t addr = abase + (mrow + (lane & 15)) * 144 + (ks * 16 + (lane >> 4) * 8) * 2;
                LDSM_X4(a[ks], addr);
            }
#pragma unroll
            for (int nbl = 0; nbl < 2; nbl++)
#pragma unroll
                for (int ks = 0; ks < 4; ks++) {
                    MMA16816(d[ms][nbl * 2],     a[ks], bb[nbl][ks][0], bb[nbl][ks][1]);
                    MMA16816(d[ms][nbl * 2 + 1], a[ks], bb[nbl][ks][2], bb[nbl][ks][3]);
                }
        }
        MBAR_ARRIVE(sb + 32 + 8 * s);
        if (tid == 0 && tp + 4 < 18) {
            MBAR_WAIT(sb + 32 + 8 * s, (tp >> 2) & 1);
            MBAR_EXPECT(sb + 8 * s, C3_WSTG);
            BULK_G2S(sb + C3_SW + s * C3_WSTG, (const char*)g_w3s + (tp + 4) * (size_t)C3_WSTG, C3_WSTG, sb + 8 * s);
        }
    }

    float psx[4], psy[4];
#pragma unroll
    for (int nb = 0; nb < 4; nb++) {
        int co = wn * 32 + nb * 8 + tig * 2;
        float2 bias = *reinterpret_cast<const float2*>(b3v + co);
        float sx = 0.0f, sy = 0.0f;
#pragma unroll
        for (int ms = 0; ms < 4; ms++)
#pragma unroll
            for (int hz = 0; hz < 2; hz++) {
                int t = t0 + wm * 64 + ms * 16 + gid + hz * 8;
                if (t < T3) {
                    sx += fmaxf(d[ms][nb][hz * 2]     + bias.x, 0.0f);
                    sy += fmaxf(d[ms][nb][hz * 2 + 1] + bias.y, 0.0f);
                }
            }
        psx[nb] = sx; psy[nb] = sy;
    }
#pragma unroll
    for (int off = 4; off < 32; off <<= 1)
#pragma unroll
        for (int nb = 0; nb < 4; nb++) {
            psx[nb] += __shfl_xor_sync(0xffffffffu, psx[nb], off);
            psy[nb] += __shfl_xor_sync(0xffffffffu, psy[nb], off);
        }
    if (lane < 4) {
#pragma unroll
        for (int nb = 0; nb < 4; nb++) {
            int co = wn * 32 + nb * 8 + lane * 2;
            spool[wm * 128 + co]     = psx[nb];
            spool[wm * 128 + co + 1] = psy[nb];
        }
    }
    __syncthreads();
    if (tid < 128)
        g_poolpart[(b * NPB + blockIdx.x) * CH3 + tid] = spool[tid] + spool[128 + tid];
}

// ---------------- head: coalesced GEMV via transposed wl ----------------
__global__ void head_kernel(const float* __restrict__ bl) {
    __shared__ float sp[128];
    __shared__ float s_amp[64];
    __shared__ float s_sum;
    int b = blockIdx.x, j = threadIdx.x;
    float s = 0.0f;
    for (int p = 0; p < NPB; p++) s += g_poolpart[(b * NPB + p) * CH3 + j];
    sp[j] = s * (1.0f / 8000.0f);
    __syncthreads();
    float dot = __ldg(bl + j);
    for (int c = 0; c < 128; c++) dot = fmaf(sp[c], g_wlt[c * 128 + j], dot);
    if (j < 64) s_amp[j] = fmaxf(dot, 0.0f);
    __syncthreads();
    if (j == 0) {
        float t = 0.0f;
        for (int h = 0; h < 64; h++) t += s_amp[h];
        s_sum = t + 1e-6f;
    }
    __syncthreads();
    if (j < 64) g_amps[b * 64 + j] = s_amp[j] / s_sum;
    else        g_nmag[b * 64 + (j - 64)] = dot;
}

// ---------------- synth: packed f32x2 harmonic pairs ----------------
__global__ __launch_bounds__(256) void synth_kernel(const float* __restrict__ f0,
                                                    const float* __restrict__ wn,
                                                    float* __restrict__ out) {
    __shared__ __align__(16) float s_amps[64];
    __shared__ float s_nm[64];
    int b = blockIdx.y;
    if (threadIdx.x < 64)       s_amps[threadIdx.x]    = g_amps[b * 64 + threadIdx.x];
    else if (threadIdx.x < 128) s_nm[threadIdx.x - 64] = g_nmag[b * 64 + threadIdx.x - 64];
    __syncthreads();
    int t = blockIdx.x * 256 + threadIdx.x;

    constexpr float DELTA  = 4.0f / 63999.0f;
    constexpr float TWO_PI = 6.283185307179586f;
    float tf  = (float)t * DELTA;
    float a   = TWO_PI * f0[(size_t)b * T0 + t];

    constexpr double PIO2_D = 1.5707963267948966192313216916397514;
    constexpr float RC1 = (float)PIO2_D;
    constexpr float RC2 = (float)(PIO2_D - (double)RC1);
    constexpr float INV_PIO2 = 0.63661977236758134308f;
    constexpr float MAGIC = 12582912.0f;

    const ull ONE2   = pk2(1.0f, 1.0f);
    const ull ZERO2  = 0ULL;
    const ull INV2   = pk2(INV_PIO2, INV_PIO2);
    const ull MAG2   = pk2(MAGIC, MAGIC);
    const ull NMAG2  = pk2(-MAGIC, -MAGIC);
    const ull NRC1_2 = pk2(-RC1, -RC1);
    const ull NRC2_2 = pk2(-RC2, -RC2);
    const ull SC1_2  = pk2(-1.9515295891e-4f, -1.9515295891e-4f);
    const ull SC2_2  = pk2(8.3321608736e-3f,  8.3321608736e-3f);
    const ull SC3_2  = pk2(-1.6666654611e-1f, -1.6666654611e-1f);
    const ull CC1_2  = pk2(2.443315711809948e-5f,  2.443315711809948e-5f);
    const ull CC2_2  = pk2(-1.388731625493765e-3f, -1.388731625493765e-3f);
    const ull CC3_2  = pk2(4.166664568298827e-2f,  4.166664568298827e-2f);
    const ull NHALF2 = pk2(-0.5f, -0.5f);
    const ull TWO2   = pk2(2.0f, 2.0f);

    ull a2  = pk2(a, a);
    ull tf2 = pk2(tf, tf);
    ull h2  = pk2(1.0f, 2.0f);
    ull acc2 = ZERO2;
    const ull* amps2 = reinterpret_cast<const ull*>(s_amps);

#pragma unroll
    for (int p = 0; p < 32; p++) {
        ull bh2 = fma2(a2, h2, ZERO2);
        ull x2  = fma2(bh2, tf2, ZERO2);
        ull kr2 = fma2(x2, INV2, MAG2);
        unsigned q0 = (unsigned)kr2, q1 = (unsigned)(kr2 >> 32);
        ull kf2 = fma2(kr2, ONE2, NMAG2);
        ull r2  = fma2(kf2, NRC1_2, x2);
        r2      = fma2(kf2, NRC2_2, r2);
        ull z2  = fma2(r2, r2, ZERO2);
        ull ps2 = fma2(SC1_2, z2, SC2_2);
        ps2     = fma2(ps2, z2, SC3_2);
        ps2     = fma2(ps2, z2, ZERO2);
        ull sr2 = fma2(ps2, r2, r2);
        ull pc2 = fma2(CC1_2, z2, CC2_2);
        pc2     = fma2(pc2, z2, CC3_2);
        pc2     = fma2(pc2, z2, NHALF2);
        ull cr2 = fma2(pc2, z2, ONE2);
        unsigned s0 = (unsigned)sr2, s1 = (unsigned)(sr2 >> 32);
        unsigned c0 = (unsigned)cr2, c1 = (unsigned)(cr2 >> 32);
        unsigned v0 = (q0 & 1u) ? c0 : s0;  v0 ^= (q0 << 30) & 0x80000000u;
        unsigned v1 = (q1 & 1u) ? c1 : s1;  v1 ^= (q1 << 30) & 0x80000000u;
        ull v2 = (ull)v0 | ((ull)v1 << 32);
        acc2 = fma2(amps2[p], v2, acc2);
        h2 = fma2(h2, ONE2, TWO2);
    }
    float acc = __int_as_float((int)(unsigned)acc2)
              + __int_as_float((int)(unsigned)(acc2 >> 32));

    int bin = t / 1000;
    float shaped = wn[(size_t)b * T0 + t] * s_nm[bin];
    out[(size_t)b * T0 + t] = acc + shaped;
}

extern "C" void kernel_launch(void* const* d_in, const int* in_sizes, int n_in,
                              void* d_out, int out_size) {
    (void)in_sizes; (void)n_in; (void)out_size;
    const float* audio = (const float*)d_in[0];
    const float* f0    = (const float*)d_in[1];
    const float* wn    = (const float*)d_in[2];
    const float* w1    = (const float*)d_in[3];
    const float* b1    = (const float*)d_in[4];
    const float* w2    = (const float*)d_in[5];
    const float* b2    = (const float*)d_in[6];
    const float* w3    = (const float*)d_in[7];
    const float* b3    = (const float*)d_in[8];
    const float* wl    = (const float*)d_in[9];
    const float* bl    = (const float*)d_in[10];
    float* out = (float*)d_out;

    cudaFuncSetAttribute(conv2_mma, cudaFuncAttributeMaxDynamicSharedMemorySize, C2_SMEM);
    cudaFuncSetAttribute(conv3_mma, cudaFuncAttributeMaxDynamicSharedMemorySize, C3_SMEM);

    prep_kernel<<<64, 256>>>(w2, w3, wl);
    conv2_mma<<<dim3(63, 16), 256, C2_SMEM>>>(audio, w1, b1, b2);
    conv3_mma<<<dim3(63, 16), 256, C3_SMEM>>>(b3);
    head_kernel<<<16, 128>>>(bl);
    synth_kernel<<<dim3(250, 16), 256>>>(f0, wn, out);
}